// round 14
// baseline (speedup 1.0000x reference)
#include <cuda_runtime.h>
#include <cuda_fp16.h>
#include <math.h>
#include <stdint.h>

// ---------------------------------------------------------------------------
// GCNEncoder on fp16 tensor cores (mma.m16n8k16, fp32 accum), cp.async
// 4-stage pipeline, ldmatrix fragment loads. Fused QK projection; softmax
// fused into GEMM epilogues (ex2.f16x2 + partial rowsums; S@X computes the
// row inverse inline from partials). Prep kernels overlapped on a 2nd stream.
// Block tile 128(M) x 256(N) x 64(K); 8 warps (2m x 4n); warp tile 64x64.
// Shapes: B=32, N=1024, D=1024, D_FF=512, L=2.
// ---------------------------------------------------------------------------

#define BM 128
#define BN 256
#define A_BYTES     (128 * 144)
#define BNK_BYTES   (256 * 144)
#define STAGE_BYTES (A_BYTES + BNK_BYTES)  // 55296
#define NSTAGE 4
#define SMEM_BYTES  (NSTAGE * STAGE_BYTES) // 221184

#define EPI_NONE 0
#define EPI_RELU 1
#define EPI_EXPM 2

static const int BB   = 32;
static const int NN_  = 1024;
static const int DD   = 1024;
static const int DFF  = 512;
static const long long MTOT = 32768;

// Scratch (device globals; no allocations allowed)
__device__ __half   g_Xh [32768ll * 1024];
__device__ __half   g_QKh[32768ll * 1024];    // [ Q | K ] fused
__device__ __half   g_Sh [32ll * 1024 * 1024]; // masked exp(scores), fp16
__device__ __half   g_Ch [32768ll * 1024];
__device__ __half   g_C2h[32768ll * 1024];
__device__ __half   g_NFh[32768ll * 1024];
__device__ __half   g_Wh [5ll * 1024 * 1024];
__device__ float    g_bqk[2 * 1024];
__device__ uint32_t g_mask[32768ll * 32];
__device__ float    g_sp [32768ll * 4];       // per-colblock partial rowsums

// ---------------------------------------------------------------------------
__device__ __forceinline__ void cp_async16(uint32_t saddr, const void* g) {
    asm volatile("cp.async.cg.shared.global [%0], [%1], 16;\n" :: "r"(saddr), "l"(g));
}
__device__ __forceinline__ void cp_commit() {
    asm volatile("cp.async.commit_group;\n" ::: "memory");
}
template <int N>
__device__ __forceinline__ void cp_wait() {
    asm volatile("cp.async.wait_group %0;\n" :: "n"(N) : "memory");
}
__device__ __forceinline__ void ldsm_x4(uint32_t& r0, uint32_t& r1,
                                        uint32_t& r2, uint32_t& r3, uint32_t a) {
    asm volatile("ldmatrix.sync.aligned.m8n8.x4.shared.b16 {%0,%1,%2,%3}, [%4];"
                 : "=r"(r0), "=r"(r1), "=r"(r2), "=r"(r3) : "r"(a));
}
__device__ __forceinline__ void ldsm_x4_t(uint32_t& r0, uint32_t& r1,
                                          uint32_t& r2, uint32_t& r3, uint32_t a) {
    asm volatile("ldmatrix.sync.aligned.m8n8.x4.trans.shared.b16 {%0,%1,%2,%3}, [%4];"
                 : "=r"(r0), "=r"(r1), "=r"(r2), "=r"(r3) : "r"(a));
}
__device__ __forceinline__ void mma_f16(float c[4], const uint32_t a[4],
                                        const uint32_t b[2]) {
    asm volatile(
        "mma.sync.aligned.m16n8k16.row.col.f32.f16.f16.f32 "
        "{%0,%1,%2,%3}, {%4,%5,%6,%7}, {%8,%9}, {%0,%1,%2,%3};\n"
        : "+f"(c[0]), "+f"(c[1]), "+f"(c[2]), "+f"(c[3])
        : "r"(a[0]), "r"(a[1]), "r"(a[2]), "r"(a[3]),
          "r"(b[0]), "r"(b[1]));
}
__device__ __forceinline__ uint32_t ex2_h2(uint32_t x) {
    uint32_t d;
    asm("ex2.approx.f16x2 %0, %1;" : "=r"(d) : "r"(x));
    return d;
}

// ---------------------------------------------------------------------------
// fp16 GEMM. C = f(alpha * A(MxK) @ B + bias). EPI: none / relu /
// masked-exp2 (emits fp16 exp + per-block partial rowsums into psum).
// ROW_SCALE: multiply output rows by 1/sum(psum[row][0..3]) computed inline.
// B_KN=false: B rows N-major-K (ldmatrix); true: B is [K][N] (ldmatrix.trans).
// ---------------------------------------------------------------------------
template <bool B_KN, int EPI, bool BIAS, bool OUT_HALF, bool ROW_SCALE>
__global__ void __launch_bounds__(256, 1)
gemm_h(const __half* __restrict__ A, const __half* __restrict__ B,
       const float* __restrict__ bias, void* __restrict__ Cout,
       const uint32_t* __restrict__ mask, const float* __restrict__ rowpart,
       float* __restrict__ psum,
       int M, int N, int K, int lda, int ldb,
       long long sA, long long sB, long long sC, float alpha)
{
    extern __shared__ char smem[];
    const uint32_t sbase = (uint32_t)__cvta_generic_to_shared(smem);

    const int bz = blockIdx.z;
    A += (long long)bz * sA;
    B += (long long)bz * sB;

    const int tid  = threadIdx.x;
    const int lane = tid & 31;
    const int wid  = tid >> 5;
    const int warpM = wid >> 2;
    const int warpN = wid & 3;
    const int rowBase = blockIdx.y * BM;
    const int colBase = blockIdx.x * BN;

    float acc[4][8][4];
#pragma unroll
    for (int i = 0; i < 4; i++)
#pragma unroll
        for (int j = 0; j < 8; j++)
#pragma unroll
            for (int r = 0; r < 4; r++) acc[i][j][r] = 0.f;

    const int lq = lane >> 2;
    const int lr = lane & 3;

    const int ofsA = ((lane & 7) + ((lane >> 3) & 1) * 8) * 144
                   + ((lane >> 4) & 1) * 16;
    const int ofsT = ((lane & 7) + ((lane >> 4) & 1) * 8) * 528
                   + ((lane >> 3) & 1) * 16;

    const int kTiles = K / 64;

    auto issue_stage = [&](int it) {
        const uint32_t sb = sbase + (it % NSTAGE) * STAGE_BYTES;
        const int k0 = it * 64;
#pragma unroll
        for (int i = 0; i < 4; i++) {
            int gid = tid + i * 256;
            int r = gid >> 3, c = gid & 7;
            cp_async16(sb + r * 144 + c * 16,
                       &A[(long long)(rowBase + r) * lda + k0 + c * 8]);
        }
        if (!B_KN) {
#pragma unroll
            for (int i = 0; i < 8; i++) {
                int gid = tid + i * 256;
                int r = gid >> 3, c = gid & 7;
                cp_async16(sb + A_BYTES + r * 144 + c * 16,
                           &B[(long long)(colBase + r) * ldb + k0 + c * 8]);
            }
        } else {
#pragma unroll
            for (int i = 0; i < 8; i++) {
                int gid = tid + i * 256;
                int r = gid >> 5, c = gid & 31;
                cp_async16(sb + A_BYTES + r * 528 + c * 16,
                           &B[(long long)(k0 + r) * ldb + colBase + c * 8]);
            }
        }
        cp_commit();
    };

    issue_stage(0);
    if (kTiles > 1) issue_stage(1);
    if (kTiles > 2) issue_stage(2);

    for (int it = 0; it < kTiles; it++) {
        if (it + 2 < kTiles)      cp_wait<2>();
        else if (it + 1 < kTiles) cp_wait<1>();
        else                      cp_wait<0>();
        __syncthreads();
        if (it + 3 < kTiles) issue_stage(it + 3);

        const uint32_t sA_ = sbase + (it % NSTAGE) * STAGE_BYTES;
        const uint32_t sB_ = sA_ + A_BYTES;

#pragma unroll
        for (int ks = 0; ks < 4; ks++) {
            uint32_t afr[4][4];
#pragma unroll
            for (int i = 0; i < 4; i++) {
                uint32_t addr = sA_ + (uint32_t)((warpM * 64 + i * 16) * 144
                                                 + ks * 32 + ofsA);
                ldsm_x4(afr[i][0], afr[i][1], afr[i][2], afr[i][3], addr);
            }
            uint32_t bfr[8][2];
            if (!B_KN) {
#pragma unroll
                for (int p = 0; p < 4; p++) {
                    uint32_t addr = sB_ + (uint32_t)((warpN * 64 + p * 16) * 144
                                                     + ks * 32 + ofsA);
                    uint32_t r0, r1, r2, r3;
                    ldsm_x4(r0, r1, r2, r3, addr);
                    bfr[2 * p][0] = r0; bfr[2 * p + 1][0] = r1;
                    bfr[2 * p][1] = r2; bfr[2 * p + 1][1] = r3;
                }
            } else {
#pragma unroll
                for (int p = 0; p < 4; p++) {
                    uint32_t addr = sB_ + (uint32_t)(ks * 16 * 528
                                                     + (warpN * 64 + p * 16) * 2 + ofsT);
                    uint32_t r0, r1, r2, r3;
                    ldsm_x4_t(r0, r1, r2, r3, addr);
                    bfr[2 * p][0] = r0; bfr[2 * p + 1][0] = r1;
                    bfr[2 * p][1] = r2; bfr[2 * p + 1][1] = r3;
                }
            }
#pragma unroll
            for (int i = 0; i < 4; i++)
#pragma unroll
                for (int j = 0; j < 8; j++)
                    mma_f16(acc[i][j], afr[i], bfr[j]);
        }
    }

    // ---- epilogue
    if (EPI == EPI_EXPM) {
        __half* Ch = (__half*)Cout + (long long)bz * sC;
        float* spart = (float*)smem;
        __syncthreads();
#pragma unroll
        for (int i = 0; i < 4; i++) {
            int rloc0 = warpM * 64 + i * 16 + lq;
#pragma unroll
            for (int h = 0; h < 2; h++) {
                int rloc = rloc0 + 8 * h;
                int row  = rowBase + rloc;
                long long mrow = ((long long)bz * M + row) * 32;
                int w0 = (colBase + warpN * 64) >> 5;
                uint32_t mw0 = mask[mrow + w0];
                uint32_t mw1 = mask[mrow + w0 + 1];
                float s = 0.f;
#pragma unroll
                for (int j = 0; j < 8; j++) {
                    int col = colBase + warpN * 64 + j * 8 + lr * 2;
                    float vx = acc[i][j][2 * h + 0] * alpha;
                    float vy = acc[i][j][2 * h + 1] * alpha;
                    __half2 hv = __floats2half2_rn(vx, vy);
                    uint32_t e = ex2_h2(*(uint32_t*)&hv);
                    uint32_t mw = (j < 4) ? mw0 : mw1;
                    int bit = col & 31;
                    uint32_t keep = (((mw >> bit) & 1) ? 0x0000FFFFu : 0u)
                                  | (((mw >> (bit + 1)) & 1) ? 0xFFFF0000u : 0u);
                    e &= keep;
                    *(uint32_t*)&Ch[(long long)row * N + col] = e;
                    float2 f = __half22float2(*(__half2*)&e);
                    s += f.x + f.y;
                }
                s += __shfl_xor_sync(0xffffffffu, s, 1);
                s += __shfl_xor_sync(0xffffffffu, s, 2);
                if (lr == 0) spart[rloc * 4 + warpN] = s;
            }
        }
        __syncthreads();
        if (tid < 128) {
            float s = spart[tid * 4] + spart[tid * 4 + 1]
                    + spart[tid * 4 + 2] + spart[tid * 4 + 3];
            psum[((long long)bz * M + rowBase + tid) * 4 + blockIdx.x] = s;
        }
        return;
    }

    __half* Ch = (__half*)Cout + (OUT_HALF ? (long long)bz * sC : 0);
    float*  Cf = (float*)Cout + (OUT_HALF ? 0 : (long long)bz * sC);
#pragma unroll
    for (int i = 0; i < 4; i++) {
        int row0 = rowBase + warpM * 64 + i * 16 + lq;
#pragma unroll
        for (int j = 0; j < 8; j++) {
            int col = colBase + warpN * 64 + j * 8 + lr * 2;
            float b0 = 0.f, b1 = 0.f;
            if (BIAS) { b0 = bias[col]; b1 = bias[col + 1]; }
#pragma unroll
            for (int h = 0; h < 2; h++) {
                int row = row0 + 8 * h;
                float vx = acc[i][j][2 * h + 0] * alpha + b0;
                float vy = acc[i][j][2 * h + 1] * alpha + b1;
                if (EPI == EPI_RELU) { vx = fmaxf(vx, 0.f); vy = fmaxf(vy, 0.f); }
                if (ROW_SCALE) {
                    float4 p = *(const float4*)&rowpart[((long long)bz * M + row) * 4];
                    float sm = p.x + p.y + p.z + p.w;
                    float sc = (sm > 0.f) ? __frcp_rn(sm) : 0.f;
                    vx *= sc; vy *= sc;
                }
                long long r = (long long)row * N + col;
                if (OUT_HALF) *(__half2*)&Ch[r] = __floats2half2_rn(vx, vy);
                else          *(float2*)&Cf[r]  = make_float2(vx, vy);
            }
        }
    }
}

// ---------------------------------------------------------------------------
__global__ void __launch_bounds__(256)
f2h_kernel(const float* __restrict__ in, __half* __restrict__ out, long long n)
{
    long long i = ((long long)blockIdx.x * blockDim.x + threadIdx.x) * 4;
    if (i >= n) return;
    float4 v = *(const float4*)&in[i];
    *(__half2*)&out[i]     = __floats2half2_rn(v.x, v.y);
    *(__half2*)&out[i + 2] = __floats2half2_rn(v.z, v.w);
}

__global__ void __launch_bounds__(256)
transpose_f2h_kernel(const float* __restrict__ in, __half* __restrict__ out,
                     int R, int Cc, long long ostride)
{
    __shared__ float t[32][33];
    long long zi = (long long)blockIdx.z * R * Cc;
    long long zo = (long long)blockIdx.z * ostride;
    int r0 = blockIdx.y * 32, c0 = blockIdx.x * 32;
    int tx = threadIdx.x & 31, ty = threadIdx.x >> 5;
#pragma unroll
    for (int i = 0; i < 4; i++)
        t[ty + i * 8][tx] = in[zi + (long long)(r0 + ty + i * 8) * Cc + c0 + tx];
    __syncthreads();
#pragma unroll
    for (int i = 0; i < 4; i++)
        out[zo + (long long)(c0 + ty + i * 8) * R + r0 + tx] =
            __float2half_rn(t[tx][ty + i * 8]);
}

__global__ void __launch_bounds__(256)
bias_concat_kernel(const float* __restrict__ bq, const float* __restrict__ bk,
                   float* __restrict__ bqk)
{
    int i = blockIdx.x * 256 + threadIdx.x;
    if (i >= 2048) return;
    int l = i >> 10, j = i & 1023;
    bqk[i] = (j < 512) ? bq[l * 512 + j] : bk[l * 512 + j - 512];
}

__global__ void __launch_bounds__(256)
mask_pack_kernel(const float* __restrict__ rel, uint32_t* __restrict__ mask)
{
    int lane = threadIdx.x & 31;
    long long row = (long long)blockIdx.x * 8 + (threadIdx.x >> 5);
    const float* r = rel + row * 1024;
    uint32_t* m = mask + row * 32;
#pragma unroll
    for (int w = 0; w < 32; w++) {
        uint32_t bits = __ballot_sync(0xffffffffu, r[w * 32 + lane] != 0.f);
        if (lane == 0) m[w] = bits;
    }
}

// ---------------------------------------------------------------------------
__device__ __forceinline__ float block_reduce_sum(float v, float* red) {
    int lane = threadIdx.x & 31, wid = threadIdx.x >> 5;
#pragma unroll
    for (int o = 16; o > 0; o >>= 1) v += __shfl_xor_sync(0xffffffffu, v, o);
    if (lane == 0) red[wid] = v;
    __syncthreads();
    if (wid == 0) {
        float x = (lane < 8) ? red[lane] : 0.f;
#pragma unroll
        for (int o = 4; o > 0; o >>= 1) x += __shfl_xor_sync(0xffffffffu, x, o);
        if (lane == 0) red[0] = x;
    }
    __syncthreads();
    float r = red[0];
    __syncthreads();
    return r;
}

template <bool OUT_HALF>
__global__ void __launch_bounds__(256)
add_ln_kernel(const __half* __restrict__ X, const __half* __restrict__ Cx,
              const float* __restrict__ g, const float* __restrict__ b,
              void* __restrict__ outv)
{
    __shared__ float red[8];
    long long row = blockIdx.x;
    int tid = threadIdx.x;

    __half2 x0 = *(const __half2*)&X[row * 1024 + tid * 4];
    __half2 x1 = *(const __half2*)&X[row * 1024 + tid * 4 + 2];
    __half2 c0 = *(const __half2*)&Cx[row * 1024 + tid * 4];
    __half2 c1 = *(const __half2*)&Cx[row * 1024 + tid * 4 + 2];
    float v0 = __low2float(x0) + __low2float(c0);
    float v1 = __high2float(x0) + __high2float(c0);
    float v2 = __low2float(x1) + __low2float(c1);
    float v3 = __high2float(x1) + __high2float(c1);

    float sum  = block_reduce_sum(v0 + v1 + v2 + v3, red);
    float ssq  = block_reduce_sum(v0 * v0 + v1 * v1 + v2 * v2 + v3 * v3, red);
    float mean = sum * (1.f / 1024.f);
    float var  = ssq * (1.f / 1024.f) - mean * mean;
    float rstd = rsqrtf(var + 1e-5f);

    float4 gv = *(const float4*)&g[tid * 4];
    float4 bv = *(const float4*)&b[tid * 4];
    float o0 = (v0 - mean) * rstd * gv.x + bv.x;
    float o1 = (v1 - mean) * rstd * gv.y + bv.y;
    float o2 = (v2 - mean) * rstd * gv.z + bv.z;
    float o3 = (v3 - mean) * rstd * gv.w + bv.w;

    if (OUT_HALF) {
        __half* o = (__half*)outv + row * 1024 + tid * 4;
        *(__half2*)&o[0] = __floats2half2_rn(o0, o1);
        *(__half2*)&o[2] = __floats2half2_rn(o2, o3);
    } else {
        float4 o; o.x = o0; o.y = o1; o.z = o2; o.w = o3;
        *(float4*)((float*)outv + row * 1024 + tid * 4) = o;
    }
}

// ---------------------------------------------------------------------------
extern "C" void kernel_launch(void* const* d_in, const int* in_sizes, int n_in,
                              void* d_out, int out_size)
{
    const float* node_fts = (const float*)d_in[0];
    const float* rel      = (const float*)d_in[1];
    const float* W_emb    = (const float*)d_in[2];
    const float* b_emb    = (const float*)d_in[3];
    const float* Wq       = (const float*)d_in[4];
    const float* bq       = (const float*)d_in[5];
    const float* Wk       = (const float*)d_in[6];
    const float* bk       = (const float*)d_in[7];
    const float* Wc       = (const float*)d_in[8];
    const float* ln_g     = (const float*)d_in[9];
    const float* ln_b     = (const float*)d_in[10];
    float* out = (float*)d_out;

    __half *Xh, *QKh, *Sh, *Ch, *C2h, *NFh, *Wh;
    float *bqk, *SP;
    uint32_t* Mk;
    cudaGetSymbolAddress((void**)&Xh,  g_Xh);
    cudaGetSymbolAddress((void**)&QKh, g_QKh);
    cudaGetSymbolAddress((void**)&Sh,  g_Sh);
    cudaGetSymbolAddress((void**)&Ch,  g_Ch);
    cudaGetSymbolAddress((void**)&C2h, g_C2h);
    cudaGetSymbolAddress((void**)&NFh, g_NFh);
    cudaGetSymbolAddress((void**)&Wh,  g_Wh);
    cudaGetSymbolAddress((void**)&bqk, g_bqk);
    cudaGetSymbolAddress((void**)&Mk,  g_mask);
    cudaGetSymbolAddress((void**)&SP,  g_sp);

    static cudaStream_t s2 = nullptr;
    static cudaEvent_t ev1 = nullptr, ev2 = nullptr;
    static bool attr_done = false;
    if (!attr_done) {
        cudaFuncSetAttribute(gemm_h<false, EPI_RELU, true,  true,  false>,
                             cudaFuncAttributeMaxDynamicSharedMemorySize, SMEM_BYTES);
        cudaFuncSetAttribute(gemm_h<false, EPI_NONE, true,  true,  false>,
                             cudaFuncAttributeMaxDynamicSharedMemorySize, SMEM_BYTES);
        cudaFuncSetAttribute(gemm_h<false, EPI_EXPM, false, true,  false>,
                             cudaFuncAttributeMaxDynamicSharedMemorySize, SMEM_BYTES);
        cudaFuncSetAttribute(gemm_h<true,  EPI_NONE, false, true,  true >,
                             cudaFuncAttributeMaxDynamicSharedMemorySize, SMEM_BYTES);
        cudaFuncSetAttribute(gemm_h<false, EPI_NONE, false, true,  false>,
                             cudaFuncAttributeMaxDynamicSharedMemorySize, SMEM_BYTES);
        cudaStreamCreateWithFlags(&s2, cudaStreamNonBlocking);
        cudaEventCreateWithFlags(&ev1, cudaEventDisableTiming);
        cudaEventCreateWithFlags(&ev2, cudaEventDisableTiming);
        attr_done = true;
    }

    dim3 blk(256);
    // exp(s/sqrt(dff)) = exp2(s * log2(e)/sqrt(dff))
    const float alpha_exp = 1.4426950408889634f / sqrtf((float)DFF);

    __half* WembT = Wh;                     // [1024][1024]
    __half* WqkT  = Wh + 1024ll * 1024;     // [2][1024][1024]
    __half* WcT   = Wh + 3072ll * 1024;     // [2][1024][1024]

    // ---- Fork: side-stream prep (mask pack, QK/C weight transposes, biases)
    cudaEventRecord(ev1, 0);
    cudaStreamWaitEvent(s2, ev1, 0);
    mask_pack_kernel<<<(int)(MTOT / 8), blk, 0, s2>>>(rel, Mk);
    transpose_f2h_kernel<<<dim3(16, 32, 2), blk, 0, s2>>>(Wq, WqkT, 1024, 512,
                                                          1024ll * 1024);
    transpose_f2h_kernel<<<dim3(16, 32, 2), blk, 0, s2>>>(Wk, WqkT + 512ll * 1024,
                                                          1024, 512, 1024ll * 1024);
    transpose_f2h_kernel<<<dim3(32, 32, 2), blk, 0, s2>>>(Wc, WcT, 1024, 1024,
                                                          1024ll * 1024);
    bias_concat_kernel<<<8, blk, 0, s2>>>(bq, bk, bqk);
    cudaEventRecord(ev2, s2);

    // ---- Main stream: embedding path
    f2h_kernel<<<(int)(MTOT * DD / 1024), blk>>>(node_fts, NFh, MTOT * DD);
    transpose_f2h_kernel<<<dim3(32, 32, 1), blk>>>(W_emb, WembT, 1024, 1024, 0);

    // Embedding: X = h(relu(NF @ W_emb + b_emb))
    gemm_h<false, EPI_RELU, true, true, false>
        <<<dim3(DD / BN, (int)(MTOT / BM), 1), blk, SMEM_BYTES>>>(
            NFh, WembT, b_emb, Xh, nullptr, nullptr, nullptr,
            (int)MTOT, DD, DD, DD, DD, 0, 0, 0, 1.0f);

    // ---- Join: side-stream prep must be done before QK GEMM / scores
    cudaStreamWaitEvent(0, ev2, 0);

    for (int l = 0; l < 2; l++) {
        const __half* WqkTl = WqkT + (long long)l * 1024 * 1024;
        const __half* WcTl  = WcT + (long long)l * DD * DD;
        const float*  bqkl  = bqk + (long long)l * 1024;
        const float*  gl    = ln_g + (long long)l * DD;
        const float*  bl    = ln_b + (long long)l * DD;

        // [Q|K] = h(X @ [Wq|Wk] + [bq|bk])
        gemm_h<false, EPI_NONE, true, true, false>
            <<<dim3(1024 / BN, (int)(MTOT / BM), 1), blk, SMEM_BYTES>>>(
                Xh, WqkTl, bqkl, QKh, nullptr, nullptr, nullptr,
                (int)MTOT, 1024, DD, DD, DD, 0, 0, 0, 1.0f);

        // Sh = mask ? exp(Q@K^T / sqrt(dff)) : 0  + partial rowsums -> SP
        gemm_h<false, EPI_EXPM, false, true, false>
            <<<dim3(NN_ / BN, NN_ / BM, BB), blk, SMEM_BYTES>>>(
                QKh, QKh + 512, nullptr, Sh, Mk, nullptr, SP,
                NN_, NN_, DFF, 1024, 1024,
                (long long)NN_ * 1024, (long long)NN_ * 1024,
                (long long)NN_ * NN_, alpha_exp);

        // C = h((Sh @ X) * inv_rowsum)  (inverse computed inline from SP)
        gemm_h<true, EPI_NONE, false, true, true>
            <<<dim3(DD / BN, NN_ / BM, BB), blk, SMEM_BYTES>>>(
                Sh, Xh, nullptr, Ch, nullptr, SP, nullptr,
                NN_, DD, NN_, 1024, 1024,
                (long long)NN_ * NN_, (long long)NN_ * DD,
                (long long)NN_ * DD, 1.0f);

        // C2(fp16) = C @ Wc
        gemm_h<false, EPI_NONE, false, true, false>
            <<<dim3(DD / BN, (int)(MTOT / BM), 1), blk, SMEM_BYTES>>>(
                Ch, WcTl, nullptr, C2h, nullptr, nullptr, nullptr,
                (int)MTOT, DD, DD, DD, DD, 0, 0, 0, 1.0f);

        // X = LN(X + C2): layer0 -> fp16 X, layer1 -> f32 d_out
        if (l == 0) add_ln_kernel<true ><<<(int)MTOT, blk>>>(Xh, C2h, gl, bl, Xh);
        else        add_ln_kernel<false><<<(int)MTOT, blk>>>(Xh, C2h, gl, bl, out);
    }
}

// round 15
// speedup vs baseline: 1.0148x; 1.0148x over previous
#include <cuda_runtime.h>
#include <cuda_fp16.h>
#include <math.h>
#include <stdint.h>

// ---------------------------------------------------------------------------
// GCNEncoder on fp16 tensor cores (mma.m16n8k16, fp32 accum), cp.async
// 4-stage pipeline, ldmatrix fragment loads. Fused QK projection; softmax
// fused into GEMM epilogues (ex2.f16x2 + partial rowsums); S@X computes
// 1/rowsum inline from partials (hoisted per row). Single stream.
// Block tile 128(M) x 256(N) x 64(K); 8 warps (2m x 4n); warp tile 64x64.
// Shapes: B=32, N=1024, D=1024, D_FF=512, L=2.
// ---------------------------------------------------------------------------

#define BM 128
#define BN 256
#define A_BYTES     (128 * 144)
#define BNK_BYTES   (256 * 144)
#define STAGE_BYTES (A_BYTES + BNK_BYTES)  // 55296
#define NSTAGE 4
#define SMEM_BYTES  (NSTAGE * STAGE_BYTES) // 221184

#define EPI_NONE 0
#define EPI_RELU 1
#define EPI_EXPM 2

static const int BB   = 32;
static const int NN_  = 1024;
static const int DD   = 1024;
static const int DFF  = 512;
static const long long MTOT = 32768;

// Scratch (device globals; no allocations allowed)
__device__ __half   g_Xh [32768ll * 1024];
__device__ __half   g_QKh[32768ll * 1024];    // [ Q | K ] fused
__device__ __half   g_Sh [32ll * 1024 * 1024]; // masked exp(scores), fp16
__device__ __half   g_Ch [32768ll * 1024];
__device__ __half   g_C2h[32768ll * 1024];
__device__ __half   g_NFh[32768ll * 1024];
__device__ __half   g_Wh [5ll * 1024 * 1024];
__device__ float    g_bqk[2 * 1024];
__device__ uint32_t g_mask[32768ll * 32];
__device__ float    g_sp [32768ll * 4];       // per-colblock partial rowsums

// ---------------------------------------------------------------------------
__device__ __forceinline__ void cp_async16(uint32_t saddr, const void* g) {
    asm volatile("cp.async.cg.shared.global [%0], [%1], 16;\n" :: "r"(saddr), "l"(g));
}
__device__ __forceinline__ void cp_commit() {
    asm volatile("cp.async.commit_group;\n" ::: "memory");
}
template <int N>
__device__ __forceinline__ void cp_wait() {
    asm volatile("cp.async.wait_group %0;\n" :: "n"(N) : "memory");
}
__device__ __forceinline__ void ldsm_x4(uint32_t& r0, uint32_t& r1,
                                        uint32_t& r2, uint32_t& r3, uint32_t a) {
    asm volatile("ldmatrix.sync.aligned.m8n8.x4.shared.b16 {%0,%1,%2,%3}, [%4];"
                 : "=r"(r0), "=r"(r1), "=r"(r2), "=r"(r3) : "r"(a));
}
__device__ __forceinline__ void ldsm_x4_t(uint32_t& r0, uint32_t& r1,
                                          uint32_t& r2, uint32_t& r3, uint32_t a) {
    asm volatile("ldmatrix.sync.aligned.m8n8.x4.trans.shared.b16 {%0,%1,%2,%3}, [%4];"
                 : "=r"(r0), "=r"(r1), "=r"(r2), "=r"(r3) : "r"(a));
}
__device__ __forceinline__ void mma_f16(float c[4], const uint32_t a[4],
                                        const uint32_t b[2]) {
    asm volatile(
        "mma.sync.aligned.m16n8k16.row.col.f32.f16.f16.f32 "
        "{%0,%1,%2,%3}, {%4,%5,%6,%7}, {%8,%9}, {%0,%1,%2,%3};\n"
        : "+f"(c[0]), "+f"(c[1]), "+f"(c[2]), "+f"(c[3])
        : "r"(a[0]), "r"(a[1]), "r"(a[2]), "r"(a[3]),
          "r"(b[0]), "r"(b[1]));
}
__device__ __forceinline__ uint32_t ex2_h2(uint32_t x) {
    uint32_t d;
    asm("ex2.approx.f16x2 %0, %1;" : "=r"(d) : "r"(x));
    return d;
}

// ---------------------------------------------------------------------------
// fp16 GEMM. C = f(alpha * A(MxK) @ B + bias). EPI: none / relu /
// masked-exp2 (emits fp16 exp + per-block partial rowsums into psum).
// ROW_SCALE: multiply output rows by 1/sum(rowpart[row][0..3]), computed
// once per (row) and hoisted out of the column loop.
// B_KN=false: B rows N-major-K (ldmatrix); true: B is [K][N] (ldmatrix.trans).
// ---------------------------------------------------------------------------
template <bool B_KN, int EPI, bool BIAS, bool OUT_HALF, bool ROW_SCALE>
__global__ void __launch_bounds__(256, 1)
gemm_h(const __half* __restrict__ A, const __half* __restrict__ B,
       const float* __restrict__ bias, void* __restrict__ Cout,
       const uint32_t* __restrict__ mask, const float* __restrict__ rowpart,
       float* __restrict__ psum,
       int M, int N, int K, int lda, int ldb,
       long long sA, long long sB, long long sC, float alpha)
{
    extern __shared__ char smem[];
    const uint32_t sbase = (uint32_t)__cvta_generic_to_shared(smem);

    const int bz = blockIdx.z;
    A += (long long)bz * sA;
    B += (long long)bz * sB;

    const int tid  = threadIdx.x;
    const int lane = tid & 31;
    const int wid  = tid >> 5;
    const int warpM = wid >> 2;
    const int warpN = wid & 3;
    const int rowBase = blockIdx.y * BM;
    const int colBase = blockIdx.x * BN;

    float acc[4][8][4];
#pragma unroll
    for (int i = 0; i < 4; i++)
#pragma unroll
        for (int j = 0; j < 8; j++)
#pragma unroll
            for (int r = 0; r < 4; r++) acc[i][j][r] = 0.f;

    const int lq = lane >> 2;
    const int lr = lane & 3;

    const int ofsA = ((lane & 7) + ((lane >> 3) & 1) * 8) * 144
                   + ((lane >> 4) & 1) * 16;
    const int ofsT = ((lane & 7) + ((lane >> 4) & 1) * 8) * 528
                   + ((lane >> 3) & 1) * 16;

    const int kTiles = K / 64;

    auto issue_stage = [&](int it) {
        const uint32_t sb = sbase + (it % NSTAGE) * STAGE_BYTES;
        const int k0 = it * 64;
#pragma unroll
        for (int i = 0; i < 4; i++) {
            int gid = tid + i * 256;
            int r = gid >> 3, c = gid & 7;
            cp_async16(sb + r * 144 + c * 16,
                       &A[(long long)(rowBase + r) * lda + k0 + c * 8]);
        }
        if (!B_KN) {
#pragma unroll
            for (int i = 0; i < 8; i++) {
                int gid = tid + i * 256;
                int r = gid >> 3, c = gid & 7;
                cp_async16(sb + A_BYTES + r * 144 + c * 16,
                           &B[(long long)(colBase + r) * ldb + k0 + c * 8]);
            }
        } else {
#pragma unroll
            for (int i = 0; i < 8; i++) {
                int gid = tid + i * 256;
                int r = gid >> 5, c = gid & 31;
                cp_async16(sb + A_BYTES + r * 528 + c * 16,
                           &B[(long long)(k0 + r) * ldb + colBase + c * 8]);
            }
        }
        cp_commit();
    };

    issue_stage(0);
    if (kTiles > 1) issue_stage(1);
    if (kTiles > 2) issue_stage(2);

    for (int it = 0; it < kTiles; it++) {
        if (it + 2 < kTiles)      cp_wait<2>();
        else if (it + 1 < kTiles) cp_wait<1>();
        else                      cp_wait<0>();
        __syncthreads();
        if (it + 3 < kTiles) issue_stage(it + 3);

        const uint32_t sA_ = sbase + (it % NSTAGE) * STAGE_BYTES;
        const uint32_t sB_ = sA_ + A_BYTES;

#pragma unroll
        for (int ks = 0; ks < 4; ks++) {
            uint32_t afr[4][4];
#pragma unroll
            for (int i = 0; i < 4; i++) {
                uint32_t addr = sA_ + (uint32_t)((warpM * 64 + i * 16) * 144
                                                 + ks * 32 + ofsA);
                ldsm_x4(afr[i][0], afr[i][1], afr[i][2], afr[i][3], addr);
            }
            uint32_t bfr[8][2];
            if (!B_KN) {
#pragma unroll
                for (int p = 0; p < 4; p++) {
                    uint32_t addr = sB_ + (uint32_t)((warpN * 64 + p * 16) * 144
                                                     + ks * 32 + ofsA);
                    uint32_t r0, r1, r2, r3;
                    ldsm_x4(r0, r1, r2, r3, addr);
                    bfr[2 * p][0] = r0; bfr[2 * p + 1][0] = r1;
                    bfr[2 * p][1] = r2; bfr[2 * p + 1][1] = r3;
                }
            } else {
#pragma unroll
                for (int p = 0; p < 4; p++) {
                    uint32_t addr = sB_ + (uint32_t)(ks * 16 * 528
                                                     + (warpN * 64 + p * 16) * 2 + ofsT);
                    uint32_t r0, r1, r2, r3;
                    ldsm_x4_t(r0, r1, r2, r3, addr);
                    bfr[2 * p][0] = r0; bfr[2 * p + 1][0] = r1;
                    bfr[2 * p][1] = r2; bfr[2 * p + 1][1] = r3;
                }
            }
#pragma unroll
            for (int i = 0; i < 4; i++)
#pragma unroll
                for (int j = 0; j < 8; j++)
                    mma_f16(acc[i][j], afr[i], bfr[j]);
        }
    }

    // ---- epilogue
    if (EPI == EPI_EXPM) {
        __half* Ch = (__half*)Cout + (long long)bz * sC;
        float* spart = (float*)smem;
        __syncthreads();
#pragma unroll
        for (int i = 0; i < 4; i++) {
            int rloc0 = warpM * 64 + i * 16 + lq;
#pragma unroll
            for (int h = 0; h < 2; h++) {
                int rloc = rloc0 + 8 * h;
                int row  = rowBase + rloc;
                long long mrow = ((long long)bz * M + row) * 32;
                int w0 = (colBase + warpN * 64) >> 5;
                uint32_t mw0 = mask[mrow + w0];
                uint32_t mw1 = mask[mrow + w0 + 1];
                float s = 0.f;
#pragma unroll
                for (int j = 0; j < 8; j++) {
                    int col = colBase + warpN * 64 + j * 8 + lr * 2;
                    float vx = acc[i][j][2 * h + 0] * alpha;
                    float vy = acc[i][j][2 * h + 1] * alpha;
                    __half2 hv = __floats2half2_rn(vx, vy);
                    uint32_t e = ex2_h2(*(uint32_t*)&hv);
                    uint32_t mw = (j < 4) ? mw0 : mw1;
                    int bit = col & 31;
                    uint32_t keep = (((mw >> bit) & 1) ? 0x0000FFFFu : 0u)
                                  | (((mw >> (bit + 1)) & 1) ? 0xFFFF0000u : 0u);
                    e &= keep;
                    *(uint32_t*)&Ch[(long long)row * N + col] = e;
                    float2 f = __half22float2(*(__half2*)&e);
                    s += f.x + f.y;
                }
                s += __shfl_xor_sync(0xffffffffu, s, 1);
                s += __shfl_xor_sync(0xffffffffu, s, 2);
                if (lr == 0) spart[rloc * 4 + warpN] = s;
            }
        }
        __syncthreads();
        if (tid < 128) {
            float s = spart[tid * 4] + spart[tid * 4 + 1]
                    + spart[tid * 4 + 2] + spart[tid * 4 + 3];
            psum[((long long)bz * M + rowBase + tid) * 4 + blockIdx.x] = s;
        }
        return;
    }

    __half* Ch = (__half*)Cout + (OUT_HALF ? (long long)bz * sC : 0);
    float*  Cf = (float*)Cout + (OUT_HALF ? 0 : (long long)bz * sC);
#pragma unroll
    for (int i = 0; i < 4; i++) {
        int row0 = rowBase + warpM * 64 + i * 16 + lq;
        // hoisted per-row scales (one float4 LDG per (i,h), L2-resident)
        float sc0 = 1.f, sc1 = 1.f;
        if (ROW_SCALE) {
            float4 p0 = *(const float4*)&rowpart[((long long)bz * M + row0) * 4];
            float sm0 = p0.x + p0.y + p0.z + p0.w;
            sc0 = (sm0 > 0.f) ? __frcp_rn(sm0) : 0.f;
            float4 p1 = *(const float4*)&rowpart[((long long)bz * M + row0 + 8) * 4];
            float sm1 = p1.x + p1.y + p1.z + p1.w;
            sc1 = (sm1 > 0.f) ? __frcp_rn(sm1) : 0.f;
        }
#pragma unroll
        for (int j = 0; j < 8; j++) {
            int col = colBase + warpN * 64 + j * 8 + lr * 2;
            float b0 = 0.f, b1 = 0.f;
            if (BIAS) { b0 = bias[col]; b1 = bias[col + 1]; }
#pragma unroll
            for (int h = 0; h < 2; h++) {
                int row = row0 + 8 * h;
                float vx = acc[i][j][2 * h + 0] * alpha + b0;
                float vy = acc[i][j][2 * h + 1] * alpha + b1;
                if (EPI == EPI_RELU) { vx = fmaxf(vx, 0.f); vy = fmaxf(vy, 0.f); }
                if (ROW_SCALE) {
                    float sc = (h == 0) ? sc0 : sc1;
                    vx *= sc; vy *= sc;
                }
                long long r = (long long)row * N + col;
                if (OUT_HALF) *(__half2*)&Ch[r] = __floats2half2_rn(vx, vy);
                else          *(float2*)&Cf[r]  = make_float2(vx, vy);
            }
        }
    }
}

// ---------------------------------------------------------------------------
__global__ void __launch_bounds__(256)
f2h_kernel(const float* __restrict__ in, __half* __restrict__ out, long long n)
{
    long long i = ((long long)blockIdx.x * blockDim.x + threadIdx.x) * 4;
    if (i >= n) return;
    float4 v = *(const float4*)&in[i];
    *(__half2*)&out[i]     = __floats2half2_rn(v.x, v.y);
    *(__half2*)&out[i + 2] = __floats2half2_rn(v.z, v.w);
}

__global__ void __launch_bounds__(256)
transpose_f2h_kernel(const float* __restrict__ in, __half* __restrict__ out,
                     int R, int Cc, long long ostride)
{
    __shared__ float t[32][33];
    long long zi = (long long)blockIdx.z * R * Cc;
    long long zo = (long long)blockIdx.z * ostride;
    int r0 = blockIdx.y * 32, c0 = blockIdx.x * 32;
    int tx = threadIdx.x & 31, ty = threadIdx.x >> 5;
#pragma unroll
    for (int i = 0; i < 4; i++)
        t[ty + i * 8][tx] = in[zi + (long long)(r0 + ty + i * 8) * Cc + c0 + tx];
    __syncthreads();
#pragma unroll
    for (int i = 0; i < 4; i++)
        out[zo + (long long)(c0 + ty + i * 8) * R + r0 + tx] =
            __float2half_rn(t[tx][ty + i * 8]);
}

__global__ void __launch_bounds__(256)
bias_concat_kernel(const float* __restrict__ bq, const float* __restrict__ bk,
                   float* __restrict__ bqk)
{
    int i = blockIdx.x * 256 + threadIdx.x;
    if (i >= 2048) return;
    int l = i >> 10, j = i & 1023;
    bqk[i] = (j < 512) ? bq[l * 512 + j] : bk[l * 512 + j - 512];
}

__global__ void __launch_bounds__(256)
mask_pack_kernel(const float* __restrict__ rel, uint32_t* __restrict__ mask)
{
    int lane = threadIdx.x & 31;
    long long row = (long long)blockIdx.x * 8 + (threadIdx.x >> 5);
    const float* r = rel + row * 1024;
    uint32_t* m = mask + row * 32;
#pragma unroll
    for (int w = 0; w < 32; w++) {
        uint32_t bits = __ballot_sync(0xffffffffu, r[w * 32 + lane] != 0.f);
        if (lane == 0) m[w] = bits;
    }
}

// ---------------------------------------------------------------------------
__device__ __forceinline__ float block_reduce_sum(float v, float* red) {
    int lane = threadIdx.x & 31, wid = threadIdx.x >> 5;
#pragma unroll
    for (int o = 16; o > 0; o >>= 1) v += __shfl_xor_sync(0xffffffffu, v, o);
    if (lane == 0) red[wid] = v;
    __syncthreads();
    if (wid == 0) {
        float x = (lane < 8) ? red[lane] : 0.f;
#pragma unroll
        for (int o = 4; o > 0; o >>= 1) x += __shfl_xor_sync(0xffffffffu, x, o);
        if (lane == 0) red[0] = x;
    }
    __syncthreads();
    float r = red[0];
    __syncthreads();
    return r;
}

template <bool OUT_HALF>
__global__ void __launch_bounds__(256)
add_ln_kernel(const __half* __restrict__ X, const __half* __restrict__ Cx,
              const float* __restrict__ g, const float* __restrict__ b,
              void* __restrict__ outv)
{
    __shared__ float red[8];
    long long row = blockIdx.x;
    int tid = threadIdx.x;

    __half2 x0 = *(const __half2*)&X[row * 1024 + tid * 4];
    __half2 x1 = *(const __half2*)&X[row * 1024 + tid * 4 + 2];
    __half2 c0 = *(const __half2*)&Cx[row * 1024 + tid * 4];
    __half2 c1 = *(const __half2*)&Cx[row * 1024 + tid * 4 + 2];
    float v0 = __low2float(x0) + __low2float(c0);
    float v1 = __high2float(x0) + __high2float(c0);
    float v2 = __low2float(x1) + __low2float(c1);
    float v3 = __high2float(x1) + __high2float(c1);

    float sum  = block_reduce_sum(v0 + v1 + v2 + v3, red);
    float ssq  = block_reduce_sum(v0 * v0 + v1 * v1 + v2 * v2 + v3 * v3, red);
    float mean = sum * (1.f / 1024.f);
    float var  = ssq * (1.f / 1024.f) - mean * mean;
    float rstd = rsqrtf(var + 1e-5f);

    float4 gv = *(const float4*)&g[tid * 4];
    float4 bv = *(const float4*)&b[tid * 4];
    float o0 = (v0 - mean) * rstd * gv.x + bv.x;
    float o1 = (v1 - mean) * rstd * gv.y + bv.y;
    float o2 = (v2 - mean) * rstd * gv.z + bv.z;
    float o3 = (v3 - mean) * rstd * gv.w + bv.w;

    if (OUT_HALF) {
        __half* o = (__half*)outv + row * 1024 + tid * 4;
        *(__half2*)&o[0] = __floats2half2_rn(o0, o1);
        *(__half2*)&o[2] = __floats2half2_rn(o2, o3);
    } else {
        float4 o; o.x = o0; o.y = o1; o.z = o2; o.w = o3;
        *(float4*)((float*)outv + row * 1024 + tid * 4) = o;
    }
}

// ---------------------------------------------------------------------------
extern "C" void kernel_launch(void* const* d_in, const int* in_sizes, int n_in,
                              void* d_out, int out_size)
{
    const float* node_fts = (const float*)d_in[0];
    const float* rel      = (const float*)d_in[1];
    const float* W_emb    = (const float*)d_in[2];
    const float* b_emb    = (const float*)d_in[3];
    const float* Wq       = (const float*)d_in[4];
    const float* bq       = (const float*)d_in[5];
    const float* Wk       = (const float*)d_in[6];
    const float* bk       = (const float*)d_in[7];
    const float* Wc       = (const float*)d_in[8];
    const float* ln_g     = (const float*)d_in[9];
    const float* ln_b     = (const float*)d_in[10];
    float* out = (float*)d_out;

    __half *Xh, *QKh, *Sh, *Ch, *C2h, *NFh, *Wh;
    float *bqk, *SP;
    uint32_t* Mk;
    cudaGetSymbolAddress((void**)&Xh,  g_Xh);
    cudaGetSymbolAddress((void**)&QKh, g_QKh);
    cudaGetSymbolAddress((void**)&Sh,  g_Sh);
    cudaGetSymbolAddress((void**)&Ch,  g_Ch);
    cudaGetSymbolAddress((void**)&C2h, g_C2h);
    cudaGetSymbolAddress((void**)&NFh, g_NFh);
    cudaGetSymbolAddress((void**)&Wh,  g_Wh);
    cudaGetSymbolAddress((void**)&bqk, g_bqk);
    cudaGetSymbolAddress((void**)&Mk,  g_mask);
    cudaGetSymbolAddress((void**)&SP,  g_sp);

    static bool attr_done = false;
    if (!attr_done) {
        cudaFuncSetAttribute(gemm_h<false, EPI_RELU, true,  true,  false>,
                             cudaFuncAttributeMaxDynamicSharedMemorySize, SMEM_BYTES);
        cudaFuncSetAttribute(gemm_h<false, EPI_NONE, true,  true,  false>,
                             cudaFuncAttributeMaxDynamicSharedMemorySize, SMEM_BYTES);
        cudaFuncSetAttribute(gemm_h<false, EPI_EXPM, false, true,  false>,
                             cudaFuncAttributeMaxDynamicSharedMemorySize, SMEM_BYTES);
        cudaFuncSetAttribute(gemm_h<true,  EPI_NONE, false, true,  true >,
                             cudaFuncAttributeMaxDynamicSharedMemorySize, SMEM_BYTES);
        cudaFuncSetAttribute(gemm_h<false, EPI_NONE, false, true,  false>,
                             cudaFuncAttributeMaxDynamicSharedMemorySize, SMEM_BYTES);
        attr_done = true;
    }

    dim3 blk(256);
    // exp(s/sqrt(dff)) = exp2(s * log2(e)/sqrt(dff))
    const float alpha_exp = 1.4426950408889634f / sqrtf((float)DFF);

    __half* WembT = Wh;                     // [1024][1024]
    __half* WqkT  = Wh + 1024ll * 1024;     // [2][1024][1024]
    __half* WcT   = Wh + 3072ll * 1024;     // [2][1024][1024]

    // One-time prep (single stream)
    f2h_kernel<<<(int)(MTOT * DD / 1024), blk>>>(node_fts, NFh, MTOT * DD);
    transpose_f2h_kernel<<<dim3(32, 32, 1), blk>>>(W_emb, WembT, 1024, 1024, 0);
    transpose_f2h_kernel<<<dim3(16, 32, 2), blk>>>(Wq, WqkT, 1024, 512,
                                                   1024ll * 1024);
    transpose_f2h_kernel<<<dim3(16, 32, 2), blk>>>(Wk, WqkT + 512ll * 1024,
                                                   1024, 512, 1024ll * 1024);
    transpose_f2h_kernel<<<dim3(32, 32, 2), blk>>>(Wc, WcT, 1024, 1024,
                                                   1024ll * 1024);
    bias_concat_kernel<<<8, blk>>>(bq, bk, bqk);
    mask_pack_kernel<<<(int)(MTOT / 8), blk>>>(rel, Mk);

    // Embedding: X = h(relu(NF @ W_emb + b_emb))
    gemm_h<false, EPI_RELU, true, true, false>
        <<<dim3(DD / BN, (int)(MTOT / BM), 1), blk, SMEM_BYTES>>>(
            NFh, WembT, b_emb, Xh, nullptr, nullptr, nullptr,
            (int)MTOT, DD, DD, DD, DD, 0, 0, 0, 1.0f);

    for (int l = 0; l < 2; l++) {
        const __half* WqkTl = WqkT + (long long)l * 1024 * 1024;
        const __half* WcTl  = WcT + (long long)l * DD * DD;
        const float*  bqkl  = bqk + (long long)l * 1024;
        const float*  gl    = ln_g + (long long)l * DD;
        const float*  bl    = ln_b + (long long)l * DD;

        // [Q|K] = h(X @ [Wq|Wk] + [bq|bk])
        gemm_h<false, EPI_NONE, true, true, false>
            <<<dim3(1024 / BN, (int)(MTOT / BM), 1), blk, SMEM_BYTES>>>(
                Xh, WqkTl, bqkl, QKh, nullptr, nullptr, nullptr,
                (int)MTOT, 1024, DD, DD, DD, 0, 0, 0, 1.0f);

        // Sh = mask ? exp(Q@K^T / sqrt(dff)) : 0  + partial rowsums -> SP
        gemm_h<false, EPI_EXPM, false, true, false>
            <<<dim3(NN_ / BN, NN_ / BM, BB), blk, SMEM_BYTES>>>(
                QKh, QKh + 512, nullptr, Sh, Mk, nullptr, SP,
                NN_, NN_, DFF, 1024, 1024,
                (long long)NN_ * 1024, (long long)NN_ * 1024,
                (long long)NN_ * NN_, alpha_exp);

        // C = h((Sh @ X) * inv_rowsum)  (inverse inline from SP, hoisted)
        gemm_h<true, EPI_NONE, false, true, true>
            <<<dim3(DD / BN, NN_ / BM, BB), blk, SMEM_BYTES>>>(
                Sh, Xh, nullptr, Ch, nullptr, SP, nullptr,
                NN_, DD, NN_, 1024, 1024,
                (long long)NN_ * NN_, (long long)NN_ * DD,
                (long long)NN_ * DD, 1.0f);

        // C2(fp16) = C @ Wc
        gemm_h<false, EPI_NONE, false, true, false>
            <<<dim3(DD / BN, (int)(MTOT / BM), 1), blk, SMEM_BYTES>>>(
                Ch, WcTl, nullptr, C2h, nullptr, nullptr, nullptr,
                (int)MTOT, DD, DD, DD, DD, 0, 0, 0, 1.0f);

        // X = LN(X + C2): layer0 -> fp16 X, layer1 -> f32 d_out
        if (l == 0) add_ln_kernel<true ><<<(int)MTOT, blk>>>(Xh, C2h, gl, bl, Xh);
        else        add_ln_kernel<false><<<(int)MTOT, blk>>>(Xh, C2h, gl, bl, out);
    }
}

// round 16
// speedup vs baseline: 1.0376x; 1.0225x over previous
#include <cuda_runtime.h>
#include <cuda_fp16.h>
#include <math.h>
#include <stdint.h>

// ---------------------------------------------------------------------------
// GCNEncoder on fp16 tensor cores (mma.m16n8k16, fp32 accum), cp.async
// 4-stage pipeline, ldmatrix fragment loads. Fused QK projection; softmax
// fused into GEMM epilogues (ex2.f16x2 + partial rowsums); separate tiny
// rowsum-inverse kernel; warp-per-row residual+LN. Single stream.
// Block tile 128(M) x 256(N) x 64(K); 8 warps (2m x 4n); warp tile 64x64.
// Shapes: B=32, N=1024, D=1024, D_FF=512, L=2.
// ---------------------------------------------------------------------------

#define BM 128
#define BN 256
#define A_BYTES     (128 * 144)
#define BNK_BYTES   (256 * 144)
#define STAGE_BYTES (A_BYTES + BNK_BYTES)  // 55296
#define NSTAGE 4
#define SMEM_BYTES  (NSTAGE * STAGE_BYTES) // 221184

#define EPI_NONE 0
#define EPI_RELU 1
#define EPI_EXPM 2

static const int BB   = 32;
static const int NN_  = 1024;
static const int DD   = 1024;
static const int DFF  = 512;
static const long long MTOT = 32768;

// Scratch (device globals; no allocations allowed)
__device__ __half   g_Xh [32768ll * 1024];
__device__ __half   g_QKh[32768ll * 1024];    // [ Q | K ] fused
__device__ __half   g_Sh [32ll * 1024 * 1024]; // masked exp(scores), fp16
__device__ __half   g_Ch [32768ll * 1024];
__device__ __half   g_C2h[32768ll * 1024];
__device__ __half   g_NFh[32768ll * 1024];
__device__ __half   g_Wh [5ll * 1024 * 1024];
__device__ float    g_bqk[2 * 1024];
__device__ uint32_t g_mask[32768ll * 32];
__device__ float    g_sp [32768ll * 4];       // per-colblock partial rowsums
__device__ float    g_rs [32768];             // 1/rowsum

// ---------------------------------------------------------------------------
__device__ __forceinline__ void cp_async16(uint32_t saddr, const void* g) {
    asm volatile("cp.async.cg.shared.global [%0], [%1], 16;\n" :: "r"(saddr), "l"(g));
}
__device__ __forceinline__ void cp_commit() {
    asm volatile("cp.async.commit_group;\n" ::: "memory");
}
template <int N>
__device__ __forceinline__ void cp_wait() {
    asm volatile("cp.async.wait_group %0;\n" :: "n"(N) : "memory");
}
__device__ __forceinline__ void ldsm_x4(uint32_t& r0, uint32_t& r1,
                                        uint32_t& r2, uint32_t& r3, uint32_t a) {
    asm volatile("ldmatrix.sync.aligned.m8n8.x4.shared.b16 {%0,%1,%2,%3}, [%4];"
                 : "=r"(r0), "=r"(r1), "=r"(r2), "=r"(r3) : "r"(a));
}
__device__ __forceinline__ void ldsm_x4_t(uint32_t& r0, uint32_t& r1,
                                          uint32_t& r2, uint32_t& r3, uint32_t a) {
    asm volatile("ldmatrix.sync.aligned.m8n8.x4.trans.shared.b16 {%0,%1,%2,%3}, [%4];"
                 : "=r"(r0), "=r"(r1), "=r"(r2), "=r"(r3) : "r"(a));
}
__device__ __forceinline__ void mma_f16(float c[4], const uint32_t a[4],
                                        const uint32_t b[2]) {
    asm volatile(
        "mma.sync.aligned.m16n8k16.row.col.f32.f16.f16.f32 "
        "{%0,%1,%2,%3}, {%4,%5,%6,%7}, {%8,%9}, {%0,%1,%2,%3};\n"
        : "+f"(c[0]), "+f"(c[1]), "+f"(c[2]), "+f"(c[3])
        : "r"(a[0]), "r"(a[1]), "r"(a[2]), "r"(a[3]),
          "r"(b[0]), "r"(b[1]));
}
__device__ __forceinline__ uint32_t ex2_h2(uint32_t x) {
    uint32_t d;
    asm("ex2.approx.f16x2 %0, %1;" : "=r"(d) : "r"(x));
    return d;
}

// ---------------------------------------------------------------------------
// fp16 GEMM. C = f(alpha * A(MxK) @ B + bias). EPI: none / relu /
// masked-exp2 (emits fp16 exp + per-block partial rowsums into psum).
// ROW_SCALE multiplies output rows by rowscale[bz*M + row].
// B_KN=false: B rows N-major-K (ldmatrix); true: B is [K][N] (ldmatrix.trans).
// ---------------------------------------------------------------------------
template <bool B_KN, int EPI, bool BIAS, bool OUT_HALF, bool ROW_SCALE>
__global__ void __launch_bounds__(256, 1)
gemm_h(const __half* __restrict__ A, const __half* __restrict__ B,
       const float* __restrict__ bias, void* __restrict__ Cout,
       const uint32_t* __restrict__ mask, const float* __restrict__ rowscale,
       float* __restrict__ psum,
       int M, int N, int K, int lda, int ldb,
       long long sA, long long sB, long long sC, float alpha)
{
    extern __shared__ char smem[];
    const uint32_t sbase = (uint32_t)__cvta_generic_to_shared(smem);

    const int bz = blockIdx.z;
    A += (long long)bz * sA;
    B += (long long)bz * sB;

    const int tid  = threadIdx.x;
    const int lane = tid & 31;
    const int wid  = tid >> 5;
    const int warpM = wid >> 2;
    const int warpN = wid & 3;
    const int rowBase = blockIdx.y * BM;
    const int colBase = blockIdx.x * BN;

    float acc[4][8][4];
#pragma unroll
    for (int i = 0; i < 4; i++)
#pragma unroll
        for (int j = 0; j < 8; j++)
#pragma unroll
            for (int r = 0; r < 4; r++) acc[i][j][r] = 0.f;

    const int lq = lane >> 2;
    const int lr = lane & 3;

    const int ofsA = ((lane & 7) + ((lane >> 3) & 1) * 8) * 144
                   + ((lane >> 4) & 1) * 16;
    const int ofsT = ((lane & 7) + ((lane >> 4) & 1) * 8) * 528
                   + ((lane >> 3) & 1) * 16;

    const int kTiles = K / 64;

    auto issue_stage = [&](int it) {
        const uint32_t sb = sbase + (it % NSTAGE) * STAGE_BYTES;
        const int k0 = it * 64;
#pragma unroll
        for (int i = 0; i < 4; i++) {
            int gid = tid + i * 256;
            int r = gid >> 3, c = gid & 7;
            cp_async16(sb + r * 144 + c * 16,
                       &A[(long long)(rowBase + r) * lda + k0 + c * 8]);
        }
        if (!B_KN) {
#pragma unroll
            for (int i = 0; i < 8; i++) {
                int gid = tid + i * 256;
                int r = gid >> 3, c = gid & 7;
                cp_async16(sb + A_BYTES + r * 144 + c * 16,
                           &B[(long long)(colBase + r) * ldb + k0 + c * 8]);
            }
        } else {
#pragma unroll
            for (int i = 0; i < 8; i++) {
                int gid = tid + i * 256;
                int r = gid >> 5, c = gid & 31;
                cp_async16(sb + A_BYTES + r * 528 + c * 16,
                           &B[(long long)(k0 + r) * ldb + colBase + c * 8]);
            }
        }
        cp_commit();
    };

    issue_stage(0);
    if (kTiles > 1) issue_stage(1);
    if (kTiles > 2) issue_stage(2);

    for (int it = 0; it < kTiles; it++) {
        if (it + 2 < kTiles)      cp_wait<2>();
        else if (it + 1 < kTiles) cp_wait<1>();
        else                      cp_wait<0>();
        __syncthreads();
        if (it + 3 < kTiles) issue_stage(it + 3);

        const uint32_t sA_ = sbase + (it % NSTAGE) * STAGE_BYTES;
        const uint32_t sB_ = sA_ + A_BYTES;

#pragma unroll
        for (int ks = 0; ks < 4; ks++) {
            uint32_t afr[4][4];
#pragma unroll
            for (int i = 0; i < 4; i++) {
                uint32_t addr = sA_ + (uint32_t)((warpM * 64 + i * 16) * 144
                                                 + ks * 32 + ofsA);
                ldsm_x4(afr[i][0], afr[i][1], afr[i][2], afr[i][3], addr);
            }
            uint32_t bfr[8][2];
            if (!B_KN) {
#pragma unroll
                for (int p = 0; p < 4; p++) {
                    uint32_t addr = sB_ + (uint32_t)((warpN * 64 + p * 16) * 144
                                                     + ks * 32 + ofsA);
                    uint32_t r0, r1, r2, r3;
                    ldsm_x4(r0, r1, r2, r3, addr);
                    bfr[2 * p][0] = r0; bfr[2 * p + 1][0] = r1;
                    bfr[2 * p][1] = r2; bfr[2 * p + 1][1] = r3;
                }
            } else {
#pragma unroll
                for (int p = 0; p < 4; p++) {
                    uint32_t addr = sB_ + (uint32_t)(ks * 16 * 528
                                                     + (warpN * 64 + p * 16) * 2 + ofsT);
                    uint32_t r0, r1, r2, r3;
                    ldsm_x4_t(r0, r1, r2, r3, addr);
                    bfr[2 * p][0] = r0; bfr[2 * p + 1][0] = r1;
                    bfr[2 * p][1] = r2; bfr[2 * p + 1][1] = r3;
                }
            }
#pragma unroll
            for (int i = 0; i < 4; i++)
#pragma unroll
                for (int j = 0; j < 8; j++)
                    mma_f16(acc[i][j], afr[i], bfr[j]);
        }
    }

    // ---- epilogue
    if (EPI == EPI_EXPM) {
        __half* Ch = (__half*)Cout + (long long)bz * sC;
        float* spart = (float*)smem;
        __syncthreads();
#pragma unroll
        for (int i = 0; i < 4; i++) {
            int rloc0 = warpM * 64 + i * 16 + lq;
#pragma unroll
            for (int h = 0; h < 2; h++) {
                int rloc = rloc0 + 8 * h;
                int row  = rowBase + rloc;
                long long mrow = ((long long)bz * M + row) * 32;
                int w0 = (colBase + warpN * 64) >> 5;
                uint32_t mw0 = mask[mrow + w0];
                uint32_t mw1 = mask[mrow + w0 + 1];
                float s = 0.f;
#pragma unroll
                for (int j = 0; j < 8; j++) {
                    int col = colBase + warpN * 64 + j * 8 + lr * 2;
                    float vx = acc[i][j][2 * h + 0] * alpha;
                    float vy = acc[i][j][2 * h + 1] * alpha;
                    __half2 hv = __floats2half2_rn(vx, vy);
                    uint32_t e = ex2_h2(*(uint32_t*)&hv);
                    uint32_t mw = (j < 4) ? mw0 : mw1;
                    int bit = col & 31;
                    uint32_t keep = (((mw >> bit) & 1) ? 0x0000FFFFu : 0u)
                                  | (((mw >> (bit + 1)) & 1) ? 0xFFFF0000u : 0u);
                    e &= keep;
                    *(uint32_t*)&Ch[(long long)row * N + col] = e;
                    float2 f = __half22float2(*(__half2*)&e);
                    s += f.x + f.y;
                }
                s += __shfl_xor_sync(0xffffffffu, s, 1);
                s += __shfl_xor_sync(0xffffffffu, s, 2);
                if (lr == 0) spart[rloc * 4 + warpN] = s;
            }
        }
        __syncthreads();
        if (tid < 128) {
            float s = spart[tid * 4] + spart[tid * 4 + 1]
                    + spart[tid * 4 + 2] + spart[tid * 4 + 3];
            psum[((long long)bz * M + rowBase + tid) * 4 + blockIdx.x] = s;
        }
        return;
    }

    __half* Ch = (__half*)Cout + (OUT_HALF ? (long long)bz * sC : 0);
    float*  Cf = (float*)Cout + (OUT_HALF ? 0 : (long long)bz * sC);
#pragma unroll
    for (int i = 0; i < 4; i++) {
        int row0 = rowBase + warpM * 64 + i * 16 + lq;
#pragma unroll
        for (int j = 0; j < 8; j++) {
            int col = colBase + warpN * 64 + j * 8 + lr * 2;
            float b0 = 0.f, b1 = 0.f;
            if (BIAS) { b0 = bias[col]; b1 = bias[col + 1]; }
#pragma unroll
            for (int h = 0; h < 2; h++) {
                int row = row0 + 8 * h;
                float vx = acc[i][j][2 * h + 0] * alpha + b0;
                float vy = acc[i][j][2 * h + 1] * alpha + b1;
                if (EPI == EPI_RELU) { vx = fmaxf(vx, 0.f); vy = fmaxf(vy, 0.f); }
                if (ROW_SCALE) {
                    float sc = rowscale[(long long)bz * M + row];
                    vx *= sc; vy *= sc;
                }
                long long r = (long long)row * N + col;
                if (OUT_HALF) *(__half2*)&Ch[r] = __floats2half2_rn(vx, vy);
                else          *(float2*)&Cf[r]  = make_float2(vx, vy);
            }
        }
    }
}

// ---------------------------------------------------------------------------
__global__ void __launch_bounds__(256)
f2h_kernel(const float* __restrict__ in, __half* __restrict__ out, long long n)
{
    long long i = ((long long)blockIdx.x * blockDim.x + threadIdx.x) * 4;
    if (i >= n) return;
    float4 v = *(const float4*)&in[i];
    *(__half2*)&out[i]     = __floats2half2_rn(v.x, v.y);
    *(__half2*)&out[i + 2] = __floats2half2_rn(v.z, v.w);
}

__global__ void __launch_bounds__(256)
transpose_f2h_kernel(const float* __restrict__ in, __half* __restrict__ out,
                     int R, int Cc, long long ostride)
{
    __shared__ float t[32][33];
    long long zi = (long long)blockIdx.z * R * Cc;
    long long zo = (long long)blockIdx.z * ostride;
    int r0 = blockIdx.y * 32, c0 = blockIdx.x * 32;
    int tx = threadIdx.x & 31, ty = threadIdx.x >> 5;
#pragma unroll
    for (int i = 0; i < 4; i++)
        t[ty + i * 8][tx] = in[zi + (long long)(r0 + ty + i * 8) * Cc + c0 + tx];
    __syncthreads();
#pragma unroll
    for (int i = 0; i < 4; i++)
        out[zo + (long long)(c0 + ty + i * 8) * R + r0 + tx] =
            __float2half_rn(t[tx][ty + i * 8]);
}

__global__ void __launch_bounds__(256)
bias_concat_kernel(const float* __restrict__ bq, const float* __restrict__ bk,
                   float* __restrict__ bqk)
{
    int i = blockIdx.x * 256 + threadIdx.x;
    if (i >= 2048) return;
    int l = i >> 10, j = i & 1023;
    bqk[i] = (j < 512) ? bq[l * 512 + j] : bk[l * 512 + j - 512];
}

__global__ void __launch_bounds__(256)
mask_pack_kernel(const float* __restrict__ rel, uint32_t* __restrict__ mask)
{
    int lane = threadIdx.x & 31;
    long long row = (long long)blockIdx.x * 8 + (threadIdx.x >> 5);
    const float* r = rel + row * 1024;
    uint32_t* m = mask + row * 32;
#pragma unroll
    for (int w = 0; w < 32; w++) {
        uint32_t bits = __ballot_sync(0xffffffffu, r[w * 32 + lane] != 0.f);
        if (lane == 0) m[w] = bits;
    }
}

// inv[row] = 1 / (sum of 4 partials), 0 if sum == 0.
__global__ void __launch_bounds__(256)
rowsum4_inv_kernel(const float* __restrict__ p, float* __restrict__ inv)
{
    long long r = (long long)blockIdx.x * 256 + threadIdx.x;
    float4 v = *(const float4*)&p[r * 4];
    float s = v.x + v.y + v.z + v.w;
    inv[r] = (s > 0.f) ? (1.f / s) : 0.f;
}

// ---------------------------------------------------------------------------
// Warp-per-row residual + LayerNorm: 8 rows per 256-thread block, no smem,
// no block barriers. Each lane holds 32 of the row's 1024 elements.
// OUT_HALF -> fp16 out, else f32 out.
// ---------------------------------------------------------------------------
template <bool OUT_HALF>
__global__ void __launch_bounds__(256)
add_ln_kernel(const __half* __restrict__ X, const __half* __restrict__ Cx,
              const float* __restrict__ g, const float* __restrict__ b,
              void* __restrict__ outv)
{
    const int lane = threadIdx.x & 31;
    const long long row = (long long)blockIdx.x * 8 + (threadIdx.x >> 5);
    const long long base = row * 1024;

    float v[32];
    float sum = 0.f, ssq = 0.f;
#pragma unroll
    for (int k = 0; k < 8; k++) {
        int col = k * 128 + lane * 4;
        __half2 x0 = *(const __half2*)&X [base + col];
        __half2 x1 = *(const __half2*)&X [base + col + 2];
        __half2 c0 = *(const __half2*)&Cx[base + col];
        __half2 c1 = *(const __half2*)&Cx[base + col + 2];
        float v0 = __low2float(x0) + __low2float(c0);
        float v1 = __high2float(x0) + __high2float(c0);
        float v2 = __low2float(x1) + __low2float(c1);
        float v3 = __high2float(x1) + __high2float(c1);
        v[k * 4 + 0] = v0; v[k * 4 + 1] = v1;
        v[k * 4 + 2] = v2; v[k * 4 + 3] = v3;
        sum += v0 + v1 + v2 + v3;
        ssq += v0 * v0 + v1 * v1 + v2 * v2 + v3 * v3;
    }
#pragma unroll
    for (int o = 16; o > 0; o >>= 1) {
        sum += __shfl_xor_sync(0xffffffffu, sum, o);
        ssq += __shfl_xor_sync(0xffffffffu, ssq, o);
    }
    float mean = sum * (1.f / 1024.f);
    float var  = ssq * (1.f / 1024.f) - mean * mean;
    float rstd = rsqrtf(var + 1e-5f);

#pragma unroll
    for (int k = 0; k < 8; k++) {
        int col = k * 128 + lane * 4;
        float4 gv = *(const float4*)&g[col];
        float4 bv = *(const float4*)&b[col];
        float o0 = (v[k * 4 + 0] - mean) * rstd * gv.x + bv.x;
        float o1 = (v[k * 4 + 1] - mean) * rstd * gv.y + bv.y;
        float o2 = (v[k * 4 + 2] - mean) * rstd * gv.z + bv.z;
        float o3 = (v[k * 4 + 3] - mean) * rstd * gv.w + bv.w;
        if (OUT_HALF) {
            __half* o = (__half*)outv + base + col;
            *(__half2*)&o[0] = __floats2half2_rn(o0, o1);
            *(__half2*)&o[2] = __floats2half2_rn(o2, o3);
        } else {
            float4 o; o.x = o0; o.y = o1; o.z = o2; o.w = o3;
            *(float4*)((float*)outv + base + col) = o;
        }
    }
}

// ---------------------------------------------------------------------------
extern "C" void kernel_launch(void* const* d_in, const int* in_sizes, int n_in,
                              void* d_out, int out_size)
{
    const float* node_fts = (const float*)d_in[0];
    const float* rel      = (const float*)d_in[1];
    const float* W_emb    = (const float*)d_in[2];
    const float* b_emb    = (const float*)d_in[3];
    const float* Wq       = (const float*)d_in[4];
    const float* bq       = (const float*)d_in[5];
    const float* Wk       = (const float*)d_in[6];
    const float* bk       = (const float*)d_in[7];
    const float* Wc       = (const float*)d_in[8];
    const float* ln_g     = (const float*)d_in[9];
    const float* ln_b     = (const float*)d_in[10];
    float* out = (float*)d_out;

    __half *Xh, *QKh, *Sh, *Ch, *C2h, *NFh, *Wh;
    float *bqk, *SP, *RS;
    uint32_t* Mk;
    cudaGetSymbolAddress((void**)&Xh,  g_Xh);
    cudaGetSymbolAddress((void**)&QKh, g_QKh);
    cudaGetSymbolAddress((void**)&Sh,  g_Sh);
    cudaGetSymbolAddress((void**)&Ch,  g_Ch);
    cudaGetSymbolAddress((void**)&C2h, g_C2h);
    cudaGetSymbolAddress((void**)&NFh, g_NFh);
    cudaGetSymbolAddress((void**)&Wh,  g_Wh);
    cudaGetSymbolAddress((void**)&bqk, g_bqk);
    cudaGetSymbolAddress((void**)&Mk,  g_mask);
    cudaGetSymbolAddress((void**)&SP,  g_sp);
    cudaGetSymbolAddress((void**)&RS,  g_rs);

    static bool attr_done = false;
    if (!attr_done) {
        cudaFuncSetAttribute(gemm_h<false, EPI_RELU, true,  true,  false>,
                             cudaFuncAttributeMaxDynamicSharedMemorySize, SMEM_BYTES);
        cudaFuncSetAttribute(gemm_h<false, EPI_NONE, true,  true,  false>,
                             cudaFuncAttributeMaxDynamicSharedMemorySize, SMEM_BYTES);
        cudaFuncSetAttribute(gemm_h<false, EPI_EXPM, false, true,  false>,
                             cudaFuncAttributeMaxDynamicSharedMemorySize, SMEM_BYTES);
        cudaFuncSetAttribute(gemm_h<true,  EPI_NONE, false, true,  true >,
                             cudaFuncAttributeMaxDynamicSharedMemorySize, SMEM_BYTES);
        cudaFuncSetAttribute(gemm_h<false, EPI_NONE, false, true,  false>,
                             cudaFuncAttributeMaxDynamicSharedMemorySize, SMEM_BYTES);
        attr_done = true;
    }

    dim3 blk(256);
    // exp(s/sqrt(dff)) = exp2(s * log2(e)/sqrt(dff))
    const float alpha_exp = 1.4426950408889634f / sqrtf((float)DFF);

    __half* WembT = Wh;                     // [1024][1024]
    __half* WqkT  = Wh + 1024ll * 1024;     // [2][1024][1024]
    __half* WcT   = Wh + 3072ll * 1024;     // [2][1024][1024]

    // One-time prep (single stream)
    f2h_kernel<<<(int)(MTOT * DD / 1024), blk>>>(node_fts, NFh, MTOT * DD);
    transpose_f2h_kernel<<<dim3(32, 32, 1), blk>>>(W_emb, WembT, 1024, 1024, 0);
    transpose_f2h_kernel<<<dim3(16, 32, 2), blk>>>(Wq, WqkT, 1024, 512,
                                                   1024ll * 1024);
    transpose_f2h_kernel<<<dim3(16, 32, 2), blk>>>(Wk, WqkT + 512ll * 1024,
                                                   1024, 512, 1024ll * 1024);
    transpose_f2h_kernel<<<dim3(32, 32, 2), blk>>>(Wc, WcT, 1024, 1024,
                                                   1024ll * 1024);
    bias_concat_kernel<<<8, blk>>>(bq, bk, bqk);
    mask_pack_kernel<<<(int)(MTOT / 8), blk>>>(rel, Mk);

    // Embedding: X = h(relu(NF @ W_emb + b_emb))
    gemm_h<false, EPI_RELU, true, true, false>
        <<<dim3(DD / BN, (int)(MTOT / BM), 1), blk, SMEM_BYTES>>>(
            NFh, WembT, b_emb, Xh, nullptr, nullptr, nullptr,
            (int)MTOT, DD, DD, DD, DD, 0, 0, 0, 1.0f);

    for (int l = 0; l < 2; l++) {
        const __half* WqkTl = WqkT + (long long)l * 1024 * 1024;
        const __half* WcTl  = WcT + (long long)l * DD * DD;
        const float*  bqkl  = bqk + (long long)l * 1024;
        const float*  gl    = ln_g + (long long)l * DD;
        const float*  bl    = ln_b + (long long)l * DD;

        // [Q|K] = h(X @ [Wq|Wk] + [bq|bk])
        gemm_h<false, EPI_NONE, true, true, false>
            <<<dim3(1024 / BN, (int)(MTOT / BM), 1), blk, SMEM_BYTES>>>(
                Xh, WqkTl, bqkl, QKh, nullptr, nullptr, nullptr,
                (int)MTOT, 1024, DD, DD, DD, 0, 0, 0, 1.0f);

        // Sh = mask ? exp(Q@K^T / sqrt(dff)) : 0  + partial rowsums -> SP
        gemm_h<false, EPI_EXPM, false, true, false>
            <<<dim3(NN_ / BN, NN_ / BM, BB), blk, SMEM_BYTES>>>(
                QKh, QKh + 512, nullptr, Sh, Mk, nullptr, SP,
                NN_, NN_, DFF, 1024, 1024,
                (long long)NN_ * 1024, (long long)NN_ * 1024,
                (long long)NN_ * NN_, alpha_exp);

        // inv rowsums from 4 partials per row
        rowsum4_inv_kernel<<<(int)(MTOT / 256), blk>>>(SP, RS);

        // C = h((Sh @ X) * inv_rowsum)
        gemm_h<true, EPI_NONE, false, true, true>
            <<<dim3(DD / BN, NN_ / BM, BB), blk, SMEM_BYTES>>>(
                Sh, Xh, nullptr, Ch, nullptr, RS, nullptr,
                NN_, DD, NN_, 1024, 1024,
                (long long)NN_ * NN_, (long long)NN_ * DD,
                (long long)NN_ * DD, 1.0f);

        // C2(fp16) = C @ Wc
        gemm_h<false, EPI_NONE, false, true, false>
            <<<dim3(DD / BN, (int)(MTOT / BM), 1), blk, SMEM_BYTES>>>(
                Ch, WcTl, nullptr, C2h, nullptr, nullptr, nullptr,
                (int)MTOT, DD, DD, DD, DD, 0, 0, 0, 1.0f);

        // X = LN(X + C2): layer0 -> fp16 X, layer1 -> f32 d_out
        if (l == 0) add_ln_kernel<true ><<<(int)(MTOT / 8), blk>>>(Xh, C2h, gl, bl, Xh);
        else        add_ln_kernel<false><<<(int)(MTOT / 8), blk>>>(Xh, C2h, gl, bl, out);
    }
}

// round 17
// speedup vs baseline: 1.0441x; 1.0063x over previous
#include <cuda_runtime.h>
#include <cuda_fp16.h>
#include <math.h>
#include <stdint.h>

// ---------------------------------------------------------------------------
// GCNEncoder on fp16 tensor cores (mma.m16n8k16, fp32 accum), cp.async
// 4-stage pipeline, ldmatrix fragment loads. Fused QK projection; softmax
// fused into GEMM epilogues (ex2.f16x2 + partial rowsums); separate tiny
// rowsum-inverse kernel; warp-per-row residual+LN. Prep (mask pack, QK/C
// weight transposes) overlapped with the compute-bound embedding GEMM on a
// second stream (forked AFTER f2h to avoid DRAM contention).
// Block tile 128(M) x 256(N) x 64(K); 8 warps (2m x 4n); warp tile 64x64.
// Shapes: B=32, N=1024, D=1024, D_FF=512, L=2.
// ---------------------------------------------------------------------------

#define BM 128
#define BN 256
#define A_BYTES     (128 * 144)
#define BNK_BYTES   (256 * 144)
#define STAGE_BYTES (A_BYTES + BNK_BYTES)  // 55296
#define NSTAGE 4
#define SMEM_BYTES  (NSTAGE * STAGE_BYTES) // 221184

#define EPI_NONE 0
#define EPI_RELU 1
#define EPI_EXPM 2

static const int BB   = 32;
static const int NN_  = 1024;
static const int DD   = 1024;
static const int DFF  = 512;
static const long long MTOT = 32768;

// Scratch (device globals; no allocations allowed)
__device__ __half   g_Xh [32768ll * 1024];
__device__ __half   g_QKh[32768ll * 1024];    // [ Q | K ] fused
__device__ __half   g_Sh [32ll * 1024 * 1024]; // masked exp(scores), fp16
__device__ __half   g_Ch [32768ll * 1024];
__device__ __half   g_C2h[32768ll * 1024];
__device__ __half   g_NFh[32768ll * 1024];
__device__ __half   g_Wh [5ll * 1024 * 1024];
__device__ float    g_bqk[2 * 1024];
__device__ uint32_t g_mask[32768ll * 32];
__device__ float    g_sp [32768ll * 4];       // per-colblock partial rowsums
__device__ float    g_rs [32768];             // 1/rowsum

// ---------------------------------------------------------------------------
__device__ __forceinline__ void cp_async16(uint32_t saddr, const void* g) {
    asm volatile("cp.async.cg.shared.global [%0], [%1], 16;\n" :: "r"(saddr), "l"(g));
}
__device__ __forceinline__ void cp_commit() {
    asm volatile("cp.async.commit_group;\n" ::: "memory");
}
template <int N>
__device__ __forceinline__ void cp_wait() {
    asm volatile("cp.async.wait_group %0;\n" :: "n"(N) : "memory");
}
__device__ __forceinline__ void ldsm_x4(uint32_t& r0, uint32_t& r1,
                                        uint32_t& r2, uint32_t& r3, uint32_t a) {
    asm volatile("ldmatrix.sync.aligned.m8n8.x4.shared.b16 {%0,%1,%2,%3}, [%4];"
                 : "=r"(r0), "=r"(r1), "=r"(r2), "=r"(r3) : "r"(a));
}
__device__ __forceinline__ void ldsm_x4_t(uint32_t& r0, uint32_t& r1,
                                          uint32_t& r2, uint32_t& r3, uint32_t a) {
    asm volatile("ldmatrix.sync.aligned.m8n8.x4.trans.shared.b16 {%0,%1,%2,%3}, [%4];"
                 : "=r"(r0), "=r"(r1), "=r"(r2), "=r"(r3) : "r"(a));
}
__device__ __forceinline__ void mma_f16(float c[4], const uint32_t a[4],
                                        const uint32_t b[2]) {
    asm volatile(
        "mma.sync.aligned.m16n8k16.row.col.f32.f16.f16.f32 "
        "{%0,%1,%2,%3}, {%4,%5,%6,%7}, {%8,%9}, {%0,%1,%2,%3};\n"
        : "+f"(c[0]), "+f"(c[1]), "+f"(c[2]), "+f"(c[3])
        : "r"(a[0]), "r"(a[1]), "r"(a[2]), "r"(a[3]),
          "r"(b[0]), "r"(b[1]));
}
__device__ __forceinline__ uint32_t ex2_h2(uint32_t x) {
    uint32_t d;
    asm("ex2.approx.f16x2 %0, %1;" : "=r"(d) : "r"(x));
    return d;
}

// ---------------------------------------------------------------------------
// fp16 GEMM. C = f(alpha * A(MxK) @ B + bias). EPI: none / relu /
// masked-exp2 (emits fp16 exp + per-block partial rowsums into psum).
// ROW_SCALE multiplies output rows by rowscale[bz*M + row].
// B_KN=false: B rows N-major-K (ldmatrix); true: B is [K][N] (ldmatrix.trans).
// ---------------------------------------------------------------------------
template <bool B_KN, int EPI, bool BIAS, bool OUT_HALF, bool ROW_SCALE>
__global__ void __launch_bounds__(256, 1)
gemm_h(const __half* __restrict__ A, const __half* __restrict__ B,
       const float* __restrict__ bias, void* __restrict__ Cout,
       const uint32_t* __restrict__ mask, const float* __restrict__ rowscale,
       float* __restrict__ psum,
       int M, int N, int K, int lda, int ldb,
       long long sA, long long sB, long long sC, float alpha)
{
    extern __shared__ char smem[];
    const uint32_t sbase = (uint32_t)__cvta_generic_to_shared(smem);

    const int bz = blockIdx.z;
    A += (long long)bz * sA;
    B += (long long)bz * sB;

    const int tid  = threadIdx.x;
    const int lane = tid & 31;
    const int wid  = tid >> 5;
    const int warpM = wid >> 2;
    const int warpN = wid & 3;
    const int rowBase = blockIdx.y * BM;
    const int colBase = blockIdx.x * BN;

    float acc[4][8][4];
#pragma unroll
    for (int i = 0; i < 4; i++)
#pragma unroll
        for (int j = 0; j < 8; j++)
#pragma unroll
            for (int r = 0; r < 4; r++) acc[i][j][r] = 0.f;

    const int lq = lane >> 2;
    const int lr = lane & 3;

    const int ofsA = ((lane & 7) + ((lane >> 3) & 1) * 8) * 144
                   + ((lane >> 4) & 1) * 16;
    const int ofsT = ((lane & 7) + ((lane >> 4) & 1) * 8) * 528
                   + ((lane >> 3) & 1) * 16;

    const int kTiles = K / 64;

    auto issue_stage = [&](int it) {
        const uint32_t sb = sbase + (it % NSTAGE) * STAGE_BYTES;
        const int k0 = it * 64;
#pragma unroll
        for (int i = 0; i < 4; i++) {
            int gid = tid + i * 256;
            int r = gid >> 3, c = gid & 7;
            cp_async16(sb + r * 144 + c * 16,
                       &A[(long long)(rowBase + r) * lda + k0 + c * 8]);
        }
        if (!B_KN) {
#pragma unroll
            for (int i = 0; i < 8; i++) {
                int gid = tid + i * 256;
                int r = gid >> 3, c = gid & 7;
                cp_async16(sb + A_BYTES + r * 144 + c * 16,
                           &B[(long long)(colBase + r) * ldb + k0 + c * 8]);
            }
        } else {
#pragma unroll
            for (int i = 0; i < 8; i++) {
                int gid = tid + i * 256;
                int r = gid >> 5, c = gid & 31;
                cp_async16(sb + A_BYTES + r * 528 + c * 16,
                           &B[(long long)(k0 + r) * ldb + colBase + c * 8]);
            }
        }
        cp_commit();
    };

    issue_stage(0);
    if (kTiles > 1) issue_stage(1);
    if (kTiles > 2) issue_stage(2);

    for (int it = 0; it < kTiles; it++) {
        if (it + 2 < kTiles)      cp_wait<2>();
        else if (it + 1 < kTiles) cp_wait<1>();
        else                      cp_wait<0>();
        __syncthreads();
        if (it + 3 < kTiles) issue_stage(it + 3);

        const uint32_t sA_ = sbase + (it % NSTAGE) * STAGE_BYTES;
        const uint32_t sB_ = sA_ + A_BYTES;

#pragma unroll
        for (int ks = 0; ks < 4; ks++) {
            uint32_t afr[4][4];
#pragma unroll
            for (int i = 0; i < 4; i++) {
                uint32_t addr = sA_ + (uint32_t)((warpM * 64 + i * 16) * 144
                                                 + ks * 32 + ofsA);
                ldsm_x4(afr[i][0], afr[i][1], afr[i][2], afr[i][3], addr);
            }
            uint32_t bfr[8][2];
            if (!B_KN) {
#pragma unroll
                for (int p = 0; p < 4; p++) {
                    uint32_t addr = sB_ + (uint32_t)((warpN * 64 + p * 16) * 144
                                                     + ks * 32 + ofsA);
                    uint32_t r0, r1, r2, r3;
                    ldsm_x4(r0, r1, r2, r3, addr);
                    bfr[2 * p][0] = r0; bfr[2 * p + 1][0] = r1;
                    bfr[2 * p][1] = r2; bfr[2 * p + 1][1] = r3;
                }
            } else {
#pragma unroll
                for (int p = 0; p < 4; p++) {
                    uint32_t addr = sB_ + (uint32_t)(ks * 16 * 528
                                                     + (warpN * 64 + p * 16) * 2 + ofsT);
                    uint32_t r0, r1, r2, r3;
                    ldsm_x4_t(r0, r1, r2, r3, addr);
                    bfr[2 * p][0] = r0; bfr[2 * p + 1][0] = r1;
                    bfr[2 * p][1] = r2; bfr[2 * p + 1][1] = r3;
                }
            }
#pragma unroll
            for (int i = 0; i < 4; i++)
#pragma unroll
                for (int j = 0; j < 8; j++)
                    mma_f16(acc[i][j], afr[i], bfr[j]);
        }
    }

    // ---- epilogue
    if (EPI == EPI_EXPM) {
        __half* Ch = (__half*)Cout + (long long)bz * sC;
        float* spart = (float*)smem;
        __syncthreads();
#pragma unroll
        for (int i = 0; i < 4; i++) {
            int rloc0 = warpM * 64 + i * 16 + lq;
#pragma unroll
            for (int h = 0; h < 2; h++) {
                int rloc = rloc0 + 8 * h;
                int row  = rowBase + rloc;
                long long mrow = ((long long)bz * M + row) * 32;
                int w0 = (colBase + warpN * 64) >> 5;
                uint32_t mw0 = mask[mrow + w0];
                uint32_t mw1 = mask[mrow + w0 + 1];
                float s = 0.f;
#pragma unroll
                for (int j = 0; j < 8; j++) {
                    int col = colBase + warpN * 64 + j * 8 + lr * 2;
                    float vx = acc[i][j][2 * h + 0] * alpha;
                    float vy = acc[i][j][2 * h + 1] * alpha;
                    __half2 hv = __floats2half2_rn(vx, vy);
                    uint32_t e = ex2_h2(*(uint32_t*)&hv);
                    uint32_t mw = (j < 4) ? mw0 : mw1;
                    int bit = col & 31;
                    uint32_t keep = (((mw >> bit) & 1) ? 0x0000FFFFu : 0u)
                                  | (((mw >> (bit + 1)) & 1) ? 0xFFFF0000u : 0u);
                    e &= keep;
                    *(uint32_t*)&Ch[(long long)row * N + col] = e;
                    float2 f = __half22float2(*(__half2*)&e);
                    s += f.x + f.y;
                }
                s += __shfl_xor_sync(0xffffffffu, s, 1);
                s += __shfl_xor_sync(0xffffffffu, s, 2);
                if (lr == 0) spart[rloc * 4 + warpN] = s;
            }
        }
        __syncthreads();
        if (tid < 128) {
            float s = spart[tid * 4] + spart[tid * 4 + 1]
                    + spart[tid * 4 + 2] + spart[tid * 4 + 3];
            psum[((long long)bz * M + rowBase + tid) * 4 + blockIdx.x] = s;
        }
        return;
    }

    __half* Ch = (__half*)Cout + (OUT_HALF ? (long long)bz * sC : 0);
    float*  Cf = (float*)Cout + (OUT_HALF ? 0 : (long long)bz * sC);
#pragma unroll
    for (int i = 0; i < 4; i++) {
        int row0 = rowBase + warpM * 64 + i * 16 + lq;
#pragma unroll
        for (int j = 0; j < 8; j++) {
            int col = colBase + warpN * 64 + j * 8 + lr * 2;
            float b0 = 0.f, b1 = 0.f;
            if (BIAS) { b0 = bias[col]; b1 = bias[col + 1]; }
#pragma unroll
            for (int h = 0; h < 2; h++) {
                int row = row0 + 8 * h;
                float vx = acc[i][j][2 * h + 0] * alpha + b0;
                float vy = acc[i][j][2 * h + 1] * alpha + b1;
                if (EPI == EPI_RELU) { vx = fmaxf(vx, 0.f); vy = fmaxf(vy, 0.f); }
                if (ROW_SCALE) {
                    float sc = rowscale[(long long)bz * M + row];
                    vx *= sc; vy *= sc;
                }
                long long r = (long long)row * N + col;
                if (OUT_HALF) *(__half2*)&Ch[r] = __floats2half2_rn(vx, vy);
                else          *(float2*)&Cf[r]  = make_float2(vx, vy);
            }
        }
    }
}

// ---------------------------------------------------------------------------
__global__ void __launch_bounds__(256)
f2h_kernel(const float* __restrict__ in, __half* __restrict__ out, long long n)
{
    long long i = ((long long)blockIdx.x * blockDim.x + threadIdx.x) * 4;
    if (i >= n) return;
    float4 v = *(const float4*)&in[i];
    *(__half2*)&out[i]     = __floats2half2_rn(v.x, v.y);
    *(__half2*)&out[i + 2] = __floats2half2_rn(v.z, v.w);
}

__global__ void __launch_bounds__(256)
transpose_f2h_kernel(const float* __restrict__ in, __half* __restrict__ out,
                     int R, int Cc, long long ostride)
{
    __shared__ float t[32][33];
    long long zi = (long long)blockIdx.z * R * Cc;
    long long zo = (long long)blockIdx.z * ostride;
    int r0 = blockIdx.y * 32, c0 = blockIdx.x * 32;
    int tx = threadIdx.x & 31, ty = threadIdx.x >> 5;
#pragma unroll
    for (int i = 0; i < 4; i++)
        t[ty + i * 8][tx] = in[zi + (long long)(r0 + ty + i * 8) * Cc + c0 + tx];
    __syncthreads();
#pragma unroll
    for (int i = 0; i < 4; i++)
        out[zo + (long long)(c0 + ty + i * 8) * R + r0 + tx] =
            __float2half_rn(t[tx][ty + i * 8]);
}

__global__ void __launch_bounds__(256)
bias_concat_kernel(const float* __restrict__ bq, const float* __restrict__ bk,
                   float* __restrict__ bqk)
{
    int i = blockIdx.x * 256 + threadIdx.x;
    if (i >= 2048) return;
    int l = i >> 10, j = i & 1023;
    bqk[i] = (j < 512) ? bq[l * 512 + j] : bk[l * 512 + j - 512];
}

__global__ void __launch_bounds__(256)
mask_pack_kernel(const float* __restrict__ rel, uint32_t* __restrict__ mask)
{
    int lane = threadIdx.x & 31;
    long long row = (long long)blockIdx.x * 8 + (threadIdx.x >> 5);
    const float* r = rel + row * 1024;
    uint32_t* m = mask + row * 32;
#pragma unroll
    for (int w = 0; w < 32; w++) {
        uint32_t bits = __ballot_sync(0xffffffffu, r[w * 32 + lane] != 0.f);
        if (lane == 0) m[w] = bits;
    }
}

// inv[row] = 1 / (sum of 4 partials), 0 if sum == 0.
__global__ void __launch_bounds__(256)
rowsum4_inv_kernel(const float* __restrict__ p, float* __restrict__ inv)
{
    long long r = (long long)blockIdx.x * 256 + threadIdx.x;
    float4 v = *(const float4*)&p[r * 4];
    float s = v.x + v.y + v.z + v.w;
    inv[r] = (s > 0.f) ? (1.f / s) : 0.f;
}

// ---------------------------------------------------------------------------
// Warp-per-row residual + LayerNorm: 8 rows per 256-thread block, no smem,
// no block barriers. OUT_HALF -> fp16 out, else f32 out.
// ---------------------------------------------------------------------------
template <bool OUT_HALF>
__global__ void __launch_bounds__(256)
add_ln_kernel(const __half* __restrict__ X, const __half* __restrict__ Cx,
              const float* __restrict__ g, const float* __restrict__ b,
              void* __restrict__ outv)
{
    const int lane = threadIdx.x & 31;
    const long long row = (long long)blockIdx.x * 8 + (threadIdx.x >> 5);
    const long long base = row * 1024;

    float v[32];
    float sum = 0.f, ssq = 0.f;
#pragma unroll
    for (int k = 0; k < 8; k++) {
        int col = k * 128 + lane * 4;
        __half2 x0 = *(const __half2*)&X [base + col];
        __half2 x1 = *(const __half2*)&X [base + col + 2];
        __half2 c0 = *(const __half2*)&Cx[base + col];
        __half2 c1 = *(const __half2*)&Cx[base + col + 2];
        float v0 = __low2float(x0) + __low2float(c0);
        float v1 = __high2float(x0) + __high2float(c0);
        float v2 = __low2float(x1) + __low2float(c1);
        float v3 = __high2float(x1) + __high2float(c1);
        v[k * 4 + 0] = v0; v[k * 4 + 1] = v1;
        v[k * 4 + 2] = v2; v[k * 4 + 3] = v3;
        sum += v0 + v1 + v2 + v3;
        ssq += v0 * v0 + v1 * v1 + v2 * v2 + v3 * v3;
    }
#pragma unroll
    for (int o = 16; o > 0; o >>= 1) {
        sum += __shfl_xor_sync(0xffffffffu, sum, o);
        ssq += __shfl_xor_sync(0xffffffffu, ssq, o);
    }
    float mean = sum * (1.f / 1024.f);
    float var  = ssq * (1.f / 1024.f) - mean * mean;
    float rstd = rsqrtf(var + 1e-5f);

#pragma unroll
    for (int k = 0; k < 8; k++) {
        int col = k * 128 + lane * 4;
        float4 gv = *(const float4*)&g[col];
        float4 bv = *(const float4*)&b[col];
        float o0 = (v[k * 4 + 0] - mean) * rstd * gv.x + bv.x;
        float o1 = (v[k * 4 + 1] - mean) * rstd * gv.y + bv.y;
        float o2 = (v[k * 4 + 2] - mean) * rstd * gv.z + bv.z;
        float o3 = (v[k * 4 + 3] - mean) * rstd * gv.w + bv.w;
        if (OUT_HALF) {
            __half* o = (__half*)outv + base + col;
            *(__half2*)&o[0] = __floats2half2_rn(o0, o1);
            *(__half2*)&o[2] = __floats2half2_rn(o2, o3);
        } else {
            float4 o; o.x = o0; o.y = o1; o.z = o2; o.w = o3;
            *(float4*)((float*)outv + base + col) = o;
        }
    }
}

// ---------------------------------------------------------------------------
extern "C" void kernel_launch(void* const* d_in, const int* in_sizes, int n_in,
                              void* d_out, int out_size)
{
    const float* node_fts = (const float*)d_in[0];
    const float* rel      = (const float*)d_in[1];
    const float* W_emb    = (const float*)d_in[2];
    const float* b_emb    = (const float*)d_in[3];
    const float* Wq       = (const float*)d_in[4];
    const float* bq       = (const float*)d_in[5];
    const float* Wk       = (const float*)d_in[6];
    const float* bk       = (const float*)d_in[7];
    const float* Wc       = (const float*)d_in[8];
    const float* ln_g     = (const float*)d_in[9];
    const float* ln_b     = (const float*)d_in[10];
    float* out = (float*)d_out;

    __half *Xh, *QKh, *Sh, *Ch, *C2h, *NFh, *Wh;
    float *bqk, *SP, *RS;
    uint32_t* Mk;
    cudaGetSymbolAddress((void**)&Xh,  g_Xh);
    cudaGetSymbolAddress((void**)&QKh, g_QKh);
    cudaGetSymbolAddress((void**)&Sh,  g_Sh);
    cudaGetSymbolAddress((void**)&Ch,  g_Ch);
    cudaGetSymbolAddress((void**)&C2h, g_C2h);
    cudaGetSymbolAddress((void**)&NFh, g_NFh);
    cudaGetSymbolAddress((void**)&Wh,  g_Wh);
    cudaGetSymbolAddress((void**)&bqk, g_bqk);
    cudaGetSymbolAddress((void**)&Mk,  g_mask);
    cudaGetSymbolAddress((void**)&SP,  g_sp);
    cudaGetSymbolAddress((void**)&RS,  g_rs);

    static cudaStream_t s2 = nullptr;
    static cudaEvent_t ev_f2h = nullptr, ev_prep = nullptr;
    static bool attr_done = false;
    if (!attr_done) {
        cudaFuncSetAttribute(gemm_h<false, EPI_RELU, true,  true,  false>,
                             cudaFuncAttributeMaxDynamicSharedMemorySize, SMEM_BYTES);
        cudaFuncSetAttribute(gemm_h<false, EPI_NONE, true,  true,  false>,
                             cudaFuncAttributeMaxDynamicSharedMemorySize, SMEM_BYTES);
        cudaFuncSetAttribute(gemm_h<false, EPI_EXPM, false, true,  false>,
                             cudaFuncAttributeMaxDynamicSharedMemorySize, SMEM_BYTES);
        cudaFuncSetAttribute(gemm_h<true,  EPI_NONE, false, true,  true >,
                             cudaFuncAttributeMaxDynamicSharedMemorySize, SMEM_BYTES);
        cudaFuncSetAttribute(gemm_h<false, EPI_NONE, false, true,  false>,
                             cudaFuncAttributeMaxDynamicSharedMemorySize, SMEM_BYTES);
        cudaStreamCreateWithFlags(&s2, cudaStreamNonBlocking);
        cudaEventCreateWithFlags(&ev_f2h,  cudaEventDisableTiming);
        cudaEventCreateWithFlags(&ev_prep, cudaEventDisableTiming);
        attr_done = true;
    }

    dim3 blk(256);
    // exp(s/sqrt(dff)) = exp2(s * log2(e)/sqrt(dff))
    const float alpha_exp = 1.4426950408889634f / sqrtf((float)DFF);

    __half* WembT = Wh;                     // [1024][1024]
    __half* WqkT  = Wh + 1024ll * 1024;     // [2][1024][1024]
    __half* WcT   = Wh + 3072ll * 1024;     // [2][1024][1024]

    // Main stream: big f2h first (bandwidth-bound; keep side stream idle)
    f2h_kernel<<<(int)(MTOT * DD / 1024), blk>>>(node_fts, NFh, MTOT * DD);
    cudaEventRecord(ev_f2h, 0);

    // Side stream: mask pack + QK/C weight transposes + biases, overlapping
    // with the compute-bound Wemb transpose + embedding GEMM below.
    cudaStreamWaitEvent(s2, ev_f2h, 0);
    mask_pack_kernel<<<(int)(MTOT / 8), blk, 0, s2>>>(rel, Mk);
    transpose_f2h_kernel<<<dim3(16, 32, 2), blk, 0, s2>>>(Wq, WqkT, 1024, 512,
                                                          1024ll * 1024);
    transpose_f2h_kernel<<<dim3(16, 32, 2), blk, 0, s2>>>(Wk, WqkT + 512ll * 1024,
                                                          1024, 512, 1024ll * 1024);
    transpose_f2h_kernel<<<dim3(32, 32, 2), blk, 0, s2>>>(Wc, WcT, 1024, 1024,
                                                          1024ll * 1024);
    bias_concat_kernel<<<8, blk, 0, s2>>>(bq, bk, bqk);
    cudaEventRecord(ev_prep, s2);

    // Main stream: embedding path (compute-bound GEMM hides the side stream)
    transpose_f2h_kernel<<<dim3(32, 32, 1), blk>>>(W_emb, WembT, 1024, 1024, 0);
    gemm_h<false, EPI_RELU, true, true, false>
        <<<dim3(DD / BN, (int)(MTOT / BM), 1), blk, SMEM_BYTES>>>(
            NFh, WembT, b_emb, Xh, nullptr, nullptr, nullptr,
            (int)MTOT, DD, DD, DD, DD, 0, 0, 0, 1.0f);

    // Join before anything that needs WqkT / bqk / Mk
    cudaStreamWaitEvent(0, ev_prep, 0);

    for (int l = 0; l < 2; l++) {
        const __half* WqkTl = WqkT + (long long)l * 1024 * 1024;
        const __half* WcTl  = WcT + (long long)l * DD * DD;
        const float*  bqkl  = bqk + (long long)l * 1024;
        const float*  gl    = ln_g + (long long)l * DD;
        const float*  bl    = ln_b + (long long)l * DD;

        // [Q|K] = h(X @ [Wq|Wk] + [bq|bk])
        gemm_h<false, EPI_NONE, true, true, false>
            <<<dim3(1024 / BN, (int)(MTOT / BM), 1), blk, SMEM_BYTES>>>(
                Xh, WqkTl, bqkl, QKh, nullptr, nullptr, nullptr,
                (int)MTOT, 1024, DD, DD, DD, 0, 0, 0, 1.0f);

        // Sh = mask ? exp(Q@K^T / sqrt(dff)) : 0  + partial rowsums -> SP
        gemm_h<false, EPI_EXPM, false, true, false>
            <<<dim3(NN_ / BN, NN_ / BM, BB), blk, SMEM_BYTES>>>(
                QKh, QKh + 512, nullptr, Sh, Mk, nullptr, SP,
                NN_, NN_, DFF, 1024, 1024,
                (long long)NN_ * 1024, (long long)NN_ * 1024,
                (long long)NN_ * NN_, alpha_exp);

        // inv rowsums from 4 partials per row
        rowsum4_inv_kernel<<<(int)(MTOT / 256), blk>>>(SP, RS);

        // C = h((Sh @ X) * inv_rowsum)
        gemm_h<true, EPI_NONE, false, true, true>
            <<<dim3(DD / BN, NN_ / BM, BB), blk, SMEM_BYTES>>>(
                Sh, Xh, nullptr, Ch, nullptr, RS, nullptr,
                NN_, DD, NN_, 1024, 1024,
                (long long)NN_ * NN_, (long long)NN_ * DD,
                (long long)NN_ * DD, 1.0f);

        // C2(fp16) = C @ Wc
        gemm_h<false, EPI_NONE, false, true, false>
            <<<dim3(DD / BN, (int)(MTOT / BM), 1), blk, SMEM_BYTES>>>(
                Ch, WcTl, nullptr, C2h, nullptr, nullptr, nullptr,
                (int)MTOT, DD, DD, DD, DD, 0, 0, 0, 1.0f);

        // X = LN(X + C2): layer0 -> fp16 X, layer1 -> f32 d_out
        if (l == 0) add_ln_kernel<true ><<<(int)(MTOT / 8), blk>>>(Xh, C2h, gl, bl, Xh);
        else        add_ln_kernel<false><<<(int)(MTOT / 8), blk>>>(Xh, C2h, gl, bl, out);
    }
}